// round 11
// baseline (speedup 1.0000x reference)
#include <cuda_runtime.h>
#include <math.h>
#include <stdint.h>

// ---------------- problem constants ----------------
#define NB      32
#define FH      11
#define FW      20
#define NEDGE   42
#define NANG    17
#define NPRED   77
#define NPROP   714
#define NPROPP  736         // padded to 23 full words
#define NOFF    72
#define KBACK   512
#define KCONV   1024
#define NREG    1241
#define NCLS    34
#define NPAD    1280
#define MROWS   1344
#define MPAD    1408
#define NWORDS  23
#define NSTRIPSF 71.0f
#define NMS_T   15.0f
#define KC      16
#define KSPLIT  8
#define SROW    24
#define MATOFF  3072        // 128 * SROW
#define STAGEF  12288       // 4 * MATOFF

// prep partition
#define PREP_W  (NPAD * (KCONV / 8))
#define PREP_S  (KCONV * (KBACK / 8))
#define PREP_G  (MROWS * (KBACK / 8))
#define PREP_TOTAL (PREP_W + PREP_S + PREP_G)

// ---------------- scratch ----------------
__device__ float g_featH [MPAD * KBACK];
__device__ float g_featL [MPAD * KBACK];
__device__ float g_WconvH[KCONV * KBACK];
__device__ float g_WconvL[KCONV * KBACK];
__device__ float g_convH [MPAD * KCONV];
__device__ float g_convL [MPAD * KCONV];
__device__ float g_WcH   [NPAD * KCONV];
__device__ float g_WcL   [NPAD * KCONV];
__device__ float g_bc    [NPAD];
__device__ float g_part  [KSPLIT * MPAD * NPAD];   // 57.7 MB

// ---------------- helpers ----------------
__device__ __forceinline__ void split2(float x, float& h, float& l) {
    uint32_t hb, lb;
    asm("cvt.rna.tf32.f32 %0, %1;" : "=r"(hb) : "f"(x));
    h = __uint_as_float(hb);
    float r = x - h;
    asm("cvt.rna.tf32.f32 %0, %1;" : "=r"(lb) : "f"(r));
    l = __uint_as_float(lb);
}
__device__ __forceinline__ void split8_store(const float* v, float* H, float* L) {
    float h[8], l[8];
#pragma unroll
    for (int j = 0; j < 8; j++) split2(v[j], h[j], l[j]);
    *reinterpret_cast<float4*>(H)     = make_float4(h[0], h[4], h[1], h[5]);
    *reinterpret_cast<float4*>(H + 4) = make_float4(h[2], h[6], h[3], h[7]);
    *reinterpret_cast<float4*>(L)     = make_float4(l[0], l[4], l[1], l[5]);
    *reinterpret_cast<float4*>(L + 4) = make_float4(l[2], l[6], l[3], l[7]);
}
__device__ __forceinline__ uint32_t smem_u32(const void* p) {
    uint32_t a;
    asm("{ .reg .u64 tmp; cvta.to.shared.u64 tmp, %1; cvt.u32.u64 %0, tmp; }"
        : "=r"(a) : "l"(p));
    return a;
}
#define MMA_TF32(d, a, b)                                                        \
    asm volatile("mma.sync.aligned.m16n8k8.row.col.f32.tf32.tf32.f32 "           \
        "{%0,%1,%2,%3}, {%4,%5,%6,%7}, {%8,%9}, {%0,%1,%2,%3};"                  \
        : "+f"((d)[0]), "+f"((d)[1]), "+f"((d)[2]), "+f"((d)[3])                 \
        : "r"((a)[0]), "r"((a)[1]), "r"((a)[2]), "r"((a)[3]),                    \
          "r"((b)[0]), "r"((b)[1]))
#define CPA_COMMIT() asm volatile("cp.async.commit_group;" ::: "memory")
#define CPA_WAIT1()  asm volatile("cp.async.wait_group 1;" ::: "memory")

// ---------------- fused prep ----------------
__global__ void k_prep(const float* __restrict__ Wr, const float* __restrict__ br,
                       const float* __restrict__ Wc, const float* __restrict__ bc,
                       const float* __restrict__ Wconv, const float* __restrict__ feat) {
    int i = blockIdx.x * blockDim.x + threadIdx.x;
    if (i < PREP_W) {
        int row = i >> 7, k0 = (i & 127) * 8;
        float v[8] = {0, 0, 0, 0, 0, 0, 0, 0};
        if (row < NREG) {
            *reinterpret_cast<float4*>(v)     = *reinterpret_cast<const float4*>(&Wr[(size_t)row * KCONV + k0]);
            *reinterpret_cast<float4*>(v + 4) = *reinterpret_cast<const float4*>(&Wr[(size_t)row * KCONV + k0 + 4]);
        } else if (row < NREG + NCLS) {
            *reinterpret_cast<float4*>(v)     = *reinterpret_cast<const float4*>(&Wc[(size_t)(row - NREG) * KCONV + k0]);
            *reinterpret_cast<float4*>(v + 4) = *reinterpret_cast<const float4*>(&Wc[(size_t)(row - NREG) * KCONV + k0 + 4]);
        }
        size_t o = (size_t)row * KCONV + k0;
        split8_store(v, &g_WcH[o], &g_WcL[o]);
        if (i < NPAD) {
            float b = 0.f;
            if (i < NREG)             b = br[i];
            else if (i < NREG + NCLS) b = bc[i - NREG];
            g_bc[i] = b;
        }
        return;
    }
    i -= PREP_W;
    if (i < PREP_S) {
        size_t o = (size_t)i * 8;
        float v[8];
        *reinterpret_cast<float4*>(v)     = *reinterpret_cast<const float4*>(&Wconv[o]);
        *reinterpret_cast<float4*>(v + 4) = *reinterpret_cast<const float4*>(&Wconv[o + 4]);
        split8_store(v, &g_WconvH[o], &g_WconvL[o]);
        return;
    }
    i -= PREP_S;
    if (i < PREP_G) {
        int m = i >> 6, c0 = (i & 63) * 8;
        int b = m / NEDGE, e = m % NEDGE;
        int h, w;
        if (e < FH)        { h = e;      w = 0;        }
        else if (e < 2*FH) { h = e - FH; w = FW - 1;   }
        else               { h = FH - 1; w = e - 2*FH; }
        float v[8];
#pragma unroll
        for (int j = 0; j < 8; j++)
            v[j] = feat[((size_t)(b * KBACK + c0 + j) * FH + h) * FW + w];
        size_t o = (size_t)m * KBACK + c0;
        split8_store(v, &g_featH[o], &g_featL[o]);
    }
}

// ---------------- tf32 mma.sync GEMM, 3xTF32, 2-stage cp.async, K-split x8 ----------------
__global__ __launch_bounds__(256, 2) void k_gemm_mma(
    const float* __restrict__ Ah, const float* __restrict__ Al,
    const float* __restrict__ Bh, const float* __restrict__ Bl,
    float* __restrict__ Cpart, int K, int N)
{
    extern __shared__ float smf[];
    const uint32_t sbase = smem_u32(smf);
    const int m0 = blockIdx.y * 128, n0 = blockIdx.x * 128;
    const int t = threadIdx.x, w = t >> 5, lane = t & 31;
    const int g = lane >> 2, c = lane & 3;
    const int wm = w & 3, wn = w >> 2;
    const int kbase = blockIdx.z * (K / KSPLIT);
    const int nch = (K / KSPLIT) / KC;
    float* C = Cpart + (size_t)blockIdx.z * MPAD * N;

    const float* srcs[4] = {
        Ah + (size_t)m0 * K, Al + (size_t)m0 * K,
        Bh + (size_t)n0 * K, Bl + (size_t)n0 * K };

    auto issue = [&](int ch, int st) {
        int kb = kbase + ch * KC;
#pragma unroll
        for (int i = 0; i < 8; i++) {
            int mat = i >> 1;
            int idx = t + (i & 1) * 256;
            int row = idx >> 2, j4 = idx & 3;
            const float* src = srcs[mat] + (size_t)row * K + kb + j4 * 4;
            uint32_t dst = sbase + (uint32_t)((st * STAGEF + mat * MATOFF + row * SROW + j4 * 4) << 2);
            asm volatile("cp.async.cg.shared.global [%0], [%1], 16;" :: "r"(dst), "l"(src));
        }
        CPA_COMMIT();
    };

    float acc[2][8][4];
#pragma unroll
    for (int mt = 0; mt < 2; mt++)
#pragma unroll
        for (int nt = 0; nt < 8; nt++)
#pragma unroll
            for (int e = 0; e < 4; e++) acc[mt][nt][e] = 0.f;

    // fragment base offsets in float2 units (all even element offsets)
    const int aB = ((wm * 32 + g) * SROW + 2 * c) >> 1;
    const int bB = ((wn * 64 + g) * SROW + 2 * c) >> 1;

    issue(0, 0);
    issue(1, 1);

    for (int ch = 0; ch < nch; ch++) {
        CPA_WAIT1();
        __syncthreads();

        const float2* S2 = reinterpret_cast<const float2*>(smf + (ch & 1) * STAGEF);
#pragma unroll
        for (int kb2 = 0; kb2 < KC / 2; kb2 += 4) {      // kb/2 in {0,4}
            uint32_t ah[2][4], al[2][4], bh[8][2], bl[8][2];
#pragma unroll
            for (int mt = 0; mt < 2; mt++) {
                float2 lo, hi;
                lo = S2[aB + mt * 192 + kb2];            // Ah row, Ah row+8 = +96
                hi = S2[aB + mt * 192 + 96 + kb2];
                ah[mt][0] = __float_as_uint(lo.x); ah[mt][1] = __float_as_uint(hi.x);
                ah[mt][2] = __float_as_uint(lo.y); ah[mt][3] = __float_as_uint(hi.y);
                lo = S2[aB + 1536 + mt * 192 + kb2];     // Al = +MATOFF/2
                hi = S2[aB + 1536 + mt * 192 + 96 + kb2];
                al[mt][0] = __float_as_uint(lo.x); al[mt][1] = __float_as_uint(hi.x);
                al[mt][2] = __float_as_uint(lo.y); al[mt][3] = __float_as_uint(hi.y);
            }
#pragma unroll
            for (int nt = 0; nt < 8; nt++) {
                float2 vh = S2[bB + 3072 + nt * 96 + kb2];   // Bh = +2*MATOFF/2
                float2 vl = S2[bB + 4608 + nt * 96 + kb2];   // Bl = +3*MATOFF/2
                bh[nt][0] = __float_as_uint(vh.x); bh[nt][1] = __float_as_uint(vh.y);
                bl[nt][0] = __float_as_uint(vl.x); bl[nt][1] = __float_as_uint(vl.y);
            }
#pragma unroll
            for (int mt = 0; mt < 2; mt++)
#pragma unroll
                for (int nt = 0; nt < 8; nt++)
                    MMA_TF32(acc[mt][nt], ah[mt], bh[nt]);
#pragma unroll
            for (int mt = 0; mt < 2; mt++)
#pragma unroll
                for (int nt = 0; nt < 8; nt++)
                    MMA_TF32(acc[mt][nt], ah[mt], bl[nt]);
#pragma unroll
            for (int mt = 0; mt < 2; mt++)
#pragma unroll
                for (int nt = 0; nt < 8; nt++)
                    MMA_TF32(acc[mt][nt], al[mt], bh[nt]);
        }
        __syncthreads();
        if (ch + 2 < nch) issue(ch + 2, ch & 1);
        else CPA_COMMIT();
    }

    // epilogue: raw fp32 partials
#pragma unroll
    for (int mt = 0; mt < 2; mt++) {
        int row0 = m0 + wm * 32 + mt * 16 + g;
#pragma unroll
        for (int nt = 0; nt < 8; nt++) {
            int col = n0 + wn * 64 + nt * 8 + 2 * c;
            *reinterpret_cast<float2*>(&C[(size_t)row0 * N + col])
                = make_float2(acc[mt][nt][0], acc[mt][nt][1]);
            *reinterpret_cast<float2*>(&C[(size_t)(row0 + 8) * N + col])
                = make_float2(acc[mt][nt][2], acc[mt][nt][3]);
        }
    }
}

// ---------------- reduce1: sum 8 partials + bias -> split+interleaved convH/L ----------------
__global__ void k_reduce1(const float* __restrict__ bias) {
    int i = blockIdx.x * blockDim.x + threadIdx.x;
    if (i >= MPAD * (KCONV / 8)) return;
    size_t o = (size_t)i * 8;
    int n0 = (i & 127) * 8;
    float v[8];
    *reinterpret_cast<float4*>(v)     = *reinterpret_cast<const float4*>(&g_part[o]);
    *reinterpret_cast<float4*>(v + 4) = *reinterpret_cast<const float4*>(&g_part[o + 4]);
#pragma unroll
    for (int s = 1; s < KSPLIT; s++) {
        size_t so = (size_t)s * MPAD * KCONV + o;
        float4 a = *reinterpret_cast<const float4*>(&g_part[so]);
        float4 b = *reinterpret_cast<const float4*>(&g_part[so + 4]);
        v[0] += a.x; v[1] += a.y; v[2] += a.z; v[3] += a.w;
        v[4] += b.x; v[5] += b.y; v[6] += b.z; v[7] += b.w;
    }
    float4 b0 = *reinterpret_cast<const float4*>(&bias[n0]);
    float4 b1 = *reinterpret_cast<const float4*>(&bias[n0 + 4]);
    v[0] += b0.x; v[1] += b0.y; v[2] += b0.z; v[3] += b0.w;
    v[4] += b1.x; v[5] += b1.y; v[6] += b1.z; v[7] += b1.w;
    split8_store(v, &g_convH[o], &g_convL[o]);
}

// ---------------- assemble (inline K-split reduce of gemm2 partials) ----------------
__global__ void k_assemble(const float* __restrict__ anchd, float* __restrict__ out) {
    int row = blockIdx.x;
    int b = row / NEDGE, e = row % NEDGE;
    float* prop   = out + (size_t)b * NPROP * NPRED;
    float* scores = out + (size_t)NB * NPROP * NPRED + (size_t)NB * NPROP + (size_t)b * NPROP;
    const float* p0 = g_part + (size_t)row * NPAD;
    auto rcval = [&](int n) {
        float v = g_bc[n] + p0[n];
#pragma unroll
        for (int z = 1; z < KSPLIT; z++)
            v += p0[(size_t)z * MPAD * NPAD + n];
        return v;
    };
    for (int l = threadIdx.x; l < NANG * NPRED; l += blockDim.x) {
        int a = l / NPRED, q = l % NPRED;
        int p = e * NANG + a;
        float v;
        if (q < 2)      v = rcval(NREG + a * 2 + q);
        else if (q < 4) v = anchd[(size_t)p * NPRED + q];
        else            v = anchd[(size_t)p * NPRED + q] + rcval(a * 73 + (q - 4));
        prop[(size_t)p * NPRED + q] = v;
    }
    if (threadIdx.x < NANG) {
        int a = threadIdx.x;
        int p = e * NANG + a;
        float l0 = rcval(NREG + a * 2);
        float l1 = rcval(NREG + a * 2 + 1);
        scores[p] = 1.0f / (1.0f + expf(l0 - l1));
    }
}

// ---------------- fused NMS: sort + pairs + group-scan, all in smem ----------------
// smem layout (u32 words): ssup[NPROPP][NWORDS] | sorder[NPROP] | sst[NPROP] | sen[NPROP] | ssc[NPROP] | keptm[32]
#define NMS_WORDS (NPROPP * NWORDS + 4 * NPROP + 32)
__global__ __launch_bounds__(1024) void k_nms(float* __restrict__ out) {
    extern __shared__ unsigned shm[];
    unsigned* ssup = shm;
    int*      sorder = (int*)(shm + NPROPP * NWORDS);
    float*    sst = (float*)(sorder + NPROP);
    float*    sen = sst + NPROP;
    float*    ssc = sen + NPROP;
    unsigned* keptm = (unsigned*)(ssc + NPROP);

    int b = blockIdx.x;
    int t = threadIdx.x, warp = t >> 5, lane = t & 31;
    const float* scores = out + (size_t)NB * NPROP * NPRED + (size_t)NB * NPROP + (size_t)b * NPROP;
    const float* prop   = out + (size_t)b * NPROP * NPRED;

    // phase 1: load scores, stable descending rank, fill sorted start/end
    if (t < NPROP) ssc[t] = scores[t];
    __syncthreads();
    if (t < NPROP) {
        float si = ssc[t];
        int r = 0;
        for (int j = 0; j < NPROP; j++) {
            float sj = ssc[j];
            r += (sj > si) || (sj == si && j < t);
        }
        sorder[r] = t;
        float p2 = prop[(size_t)t * NPRED + 2];
        float p4 = prop[(size_t)t * NPRED + 4];
        float st = fminf(fmaxf(rintf(p2 * NSTRIPSF), 0.0f), NSTRIPSF);
        float en = fminf(fmaxf(st + p4 - 1.0f, 0.0f), NSTRIPSF);
        sst[r] = st;
        sen[r] = en;
    }
    __syncthreads();

    // phase 2: pairwise suppression bitmatrix into smem (rows i >= NPROP zeroed)
    for (int i = warp; i < NPROPP; i += 32) {
        if (i < NPROP) {
            float si = sst[i], ei = sen[i];
            const float* xi = prop + (size_t)sorder[i] * NPRED + 5;
            for (int jw = 0; jw < NWORDS; jw++) {
                int j = jw * 32 + lane;
                bool sup = false;
                if (j < NPROP) {
                    float s  = fmaxf(si, sst[j]);
                    float e  = fminf(ei, sen[j]);
                    float cnt = e - s + 1.0f;
                    if (cnt > 0.0f) {
                        float sum = 0.0f;
                        int k0 = (int)s, k1 = (int)floorf(e);
                        if (k1 >= k0) {
                            const float* xj = prop + (size_t)sorder[j] * NPRED + 5;
                            for (int k = k0; k <= k1; k++) sum += fabsf(xi[k] - xj[k]);
                        }
                        sup = (sum / fmaxf(cnt, 1.0f)) < NMS_T;
                    }
                }
                unsigned m = __ballot_sync(0xFFFFFFFFu, sup);
                if (lane == 0) ssup[i * NWORDS + jw] = m;
            }
        } else {
            if (lane < NWORDS) ssup[i * NWORDS + lane] = 0u;
        }
    }
    __syncthreads();

    // phase 3: group-scan (warp 0). lane l owns suppressed word l (l < NWORDS).
    if (warp == 0) {
        unsigned my = 0;
        for (int w = 0; w < NWORDS; w++) {
            unsigned myw = __shfl_sync(0xFFFFFFFFu, my, w);
            int i0 = w * 32;
            unsigned rowval = ssup[(i0 + lane) * NWORDS + w];   // row (i0+lane), word w
            unsigned km = 0;
#pragma unroll
            for (int r = 0; r < 32; r++) {
                unsigned rw = __shfl_sync(0xFFFFFFFFu, rowval, r);
                if (!((myw >> r) & 1u)) {
                    km |= 1u << r;
                    if (r < 31) myw |= rw & (0xFFFFFFFFu << (r + 1));
                }
            }
            if (lane == w) my = myw;
            else if (lane > w && lane < NWORDS) {
#pragma unroll 4
                for (int r = 0; r < 32; r++)
                    if ((km >> r) & 1u) my |= ssup[(i0 + r) * NWORDS + lane];
            }
            if (lane == 0) keptm[w] = km;
        }
    }
    __syncthreads();

    // phase 4: write keep mask (original order)
    float* keep = out + (size_t)NB * NPROP * NPRED + (size_t)b * NPROP;
    if (t < NPROP)
        keep[sorder[t]] = ((keptm[t >> 5] >> (t & 31)) & 1u) ? 1.0f : 0.0f;
}

// ---------------- launcher ----------------
#define GEMM_SMEM (2 * STAGEF * 4)     // 98304
#define NMS_SMEM  (NMS_WORDS * 4)      // ~79.3 KB

extern "C" void kernel_launch(void* const* d_in, const int* in_sizes, int n_in,
                              void* d_out, int out_size) {
    const float* feat   = (const float*)d_in[0];
    const float* W_conv = (const float*)d_in[1];
    const float* b_conv = (const float*)d_in[2];
    const float* W_cls  = (const float*)d_in[3];
    const float* b_cls  = (const float*)d_in[4];
    const float* W_reg  = (const float*)d_in[5];
    const float* b_reg  = (const float*)d_in[6];
    const float* anchd  = (const float*)d_in[8];
    float* out = (float*)d_out;

    void *pFH, *pFL, *pWH, *pWL, *pCH, *pCL, *pWcH, *pWcL, *pPart;
    cudaGetSymbolAddress(&pFH,  g_featH);
    cudaGetSymbolAddress(&pFL,  g_featL);
    cudaGetSymbolAddress(&pWH,  g_WconvH);
    cudaGetSymbolAddress(&pWL,  g_WconvL);
    cudaGetSymbolAddress(&pCH,  g_convH);
    cudaGetSymbolAddress(&pCL,  g_convL);
    cudaGetSymbolAddress(&pWcH, g_WcH);
    cudaGetSymbolAddress(&pWcL, g_WcL);
    cudaGetSymbolAddress(&pPart, g_part);

    cudaFuncSetAttribute(k_gemm_mma, cudaFuncAttributeMaxDynamicSharedMemorySize, GEMM_SMEM);
    cudaFuncSetAttribute(k_nms, cudaFuncAttributeMaxDynamicSharedMemorySize, NMS_SMEM);

    k_prep<<<(PREP_TOTAL + 255) / 256, 256>>>(W_reg, b_reg, W_cls, b_cls, W_conv, feat);

    // GEMM1: feat(1408x512) @ W_conv^T -> 8 partials -> convH/L
    k_gemm_mma<<<dim3(KCONV / 128, MPAD / 128, KSPLIT), 256, GEMM_SMEM>>>(
        (const float*)pFH, (const float*)pFL, (const float*)pWH, (const float*)pWL,
        (float*)pPart, KBACK, KCONV);
    k_reduce1<<<(MPAD * (KCONV / 8) + 255) / 256, 256>>>(b_conv);

    // GEMM2: conv(1408x1024) @ Wc^T -> 8 partials (reduced inline by assemble)
    k_gemm_mma<<<dim3(NPAD / 128, MPAD / 128, KSPLIT), 256, GEMM_SMEM>>>(
        (const float*)pCH, (const float*)pCL, (const float*)pWcH, (const float*)pWcL,
        (float*)pPart, KCONV, NPAD);

    k_assemble<<<MROWS, 256>>>(anchd, out);
    k_nms<<<NB, 1024, NMS_SMEM>>>(out);
}

// round 12
// speedup vs baseline: 1.1362x; 1.1362x over previous
#include <cuda_runtime.h>
#include <math.h>
#include <stdint.h>

// ---------------- problem constants ----------------
#define NB      32
#define FH      11
#define FW      20
#define NEDGE   42
#define NANG    17
#define NPRED   77
#define NPROP   714
#define NOFF    72
#define KBACK   512
#define KCONV   1024
#define NREG    1241
#define NCLS    34
#define NPAD    1280
#define MROWS   1344
#define MPAD    1408
#define NWORDS  23
#define NSTRIPSF 71.0f
#define NMS_T   15.0f
#define NCHUNK  128
#define NCHUNKS 6
#define KC      16
#define KSPLIT  2
#define SROW    24          // smem row stride (floats), conflict-free float2 frags
#define MATOFF  3072        // 128 * SROW (A matrix region, floats)
#define BOFF    6144        // Ah+Al
#define BMAT    1536        // 64 * SROW
#define STAGEF  9216        // Ah+Al+Bh+Bl floats per stage

// prep partition (8-group indices)
#define PREP_W  (NPAD * (KCONV / 8))
#define PREP_S  (KCONV * (KBACK / 8))
#define PREP_G  (MROWS * (KBACK / 8))
#define PREP_TOTAL (PREP_W + PREP_S + PREP_G)

// ---------------- scratch ----------------
__device__ float    g_featH [MPAD * KBACK];
__device__ float    g_featL [MPAD * KBACK];
__device__ float    g_WconvH[KCONV * KBACK];
__device__ float    g_WconvL[KCONV * KBACK];
__device__ float    g_convH [MPAD * KCONV];
__device__ float    g_convL [MPAD * KCONV];
__device__ float    g_WcH   [NPAD * KCONV];
__device__ float    g_WcL   [NPAD * KCONV];
__device__ float    g_bc    [NPAD];
__device__ float    g_part  [KSPLIT * MPAD * NPAD];
__device__ int      g_order [NB * NPROP];
__device__ float    g_sstart[NB * NPROP];
__device__ float    g_send  [NB * NPROP];
__device__ float    g_sxs   [NB * NPROP * NOFF];
__device__ unsigned g_sup   [NB * NPROP * NWORDS];

// ---------------- helpers ----------------
__device__ __forceinline__ void split2(float x, float& h, float& l) {
    uint32_t hb, lb;
    asm("cvt.rna.tf32.f32 %0, %1;" : "=r"(hb) : "f"(x));
    h = __uint_as_float(hb);
    float r = x - h;
    asm("cvt.rna.tf32.f32 %0, %1;" : "=r"(lb) : "f"(r));
    l = __uint_as_float(lb);
}
__device__ __forceinline__ void split8_store(const float* v, float* H, float* L) {
    float h[8], l[8];
#pragma unroll
    for (int j = 0; j < 8; j++) split2(v[j], h[j], l[j]);
    *reinterpret_cast<float4*>(H)     = make_float4(h[0], h[4], h[1], h[5]);
    *reinterpret_cast<float4*>(H + 4) = make_float4(h[2], h[6], h[3], h[7]);
    *reinterpret_cast<float4*>(L)     = make_float4(l[0], l[4], l[1], l[5]);
    *reinterpret_cast<float4*>(L + 4) = make_float4(l[2], l[6], l[3], l[7]);
}
__device__ __forceinline__ uint32_t smem_u32(const void* p) {
    uint32_t a;
    asm("{ .reg .u64 tmp; cvta.to.shared.u64 tmp, %1; cvt.u32.u64 %0, tmp; }"
        : "=r"(a) : "l"(p));
    return a;
}
#define MMA_TF32(d, a, b)                                                        \
    asm volatile("mma.sync.aligned.m16n8k8.row.col.f32.tf32.tf32.f32 "           \
        "{%0,%1,%2,%3}, {%4,%5,%6,%7}, {%8,%9}, {%0,%1,%2,%3};"                  \
        : "+f"((d)[0]), "+f"((d)[1]), "+f"((d)[2]), "+f"((d)[3])                 \
        : "r"((a)[0]), "r"((a)[1]), "r"((a)[2]), "r"((a)[3]),                    \
          "r"((b)[0]), "r"((b)[1]))
#define CPA_COMMIT() asm volatile("cp.async.commit_group;" ::: "memory")
#define CPA_WAIT1()  asm volatile("cp.async.wait_group 1;" ::: "memory")

// ---------------- fused prep ----------------
__global__ void k_prep(const float* __restrict__ Wr, const float* __restrict__ br,
                       const float* __restrict__ Wc, const float* __restrict__ bc,
                       const float* __restrict__ Wconv, const float* __restrict__ feat) {
    int i = blockIdx.x * blockDim.x + threadIdx.x;
    if (i < PREP_W) {
        int row = i >> 7, k0 = (i & 127) * 8;
        float v[8] = {0, 0, 0, 0, 0, 0, 0, 0};
        if (row < NREG) {
            *reinterpret_cast<float4*>(v)     = *reinterpret_cast<const float4*>(&Wr[(size_t)row * KCONV + k0]);
            *reinterpret_cast<float4*>(v + 4) = *reinterpret_cast<const float4*>(&Wr[(size_t)row * KCONV + k0 + 4]);
        } else if (row < NREG + NCLS) {
            *reinterpret_cast<float4*>(v)     = *reinterpret_cast<const float4*>(&Wc[(size_t)(row - NREG) * KCONV + k0]);
            *reinterpret_cast<float4*>(v + 4) = *reinterpret_cast<const float4*>(&Wc[(size_t)(row - NREG) * KCONV + k0 + 4]);
        }
        size_t o = (size_t)row * KCONV + k0;
        split8_store(v, &g_WcH[o], &g_WcL[o]);
        if (i < NPAD) {
            float b = 0.f;
            if (i < NREG)             b = br[i];
            else if (i < NREG + NCLS) b = bc[i - NREG];
            g_bc[i] = b;
        }
        return;
    }
    i -= PREP_W;
    if (i < PREP_S) {
        size_t o = (size_t)i * 8;
        float v[8];
        *reinterpret_cast<float4*>(v)     = *reinterpret_cast<const float4*>(&Wconv[o]);
        *reinterpret_cast<float4*>(v + 4) = *reinterpret_cast<const float4*>(&Wconv[o + 4]);
        split8_store(v, &g_WconvH[o], &g_WconvL[o]);
        return;
    }
    i -= PREP_S;
    if (i < PREP_G) {
        int m = i >> 6, c0 = (i & 63) * 8;
        int b = m / NEDGE, e = m % NEDGE;
        int h, w;
        if (e < FH)        { h = e;      w = 0;        }
        else if (e < 2*FH) { h = e - FH; w = FW - 1;   }
        else               { h = FH - 1; w = e - 2*FH; }
        float v[8];
#pragma unroll
        for (int j = 0; j < 8; j++)
            v[j] = feat[((size_t)(b * KBACK + c0 + j) * FH + h) * FW + w];
        size_t o = (size_t)m * KBACK + c0;
        split8_store(v, &g_featH[o], &g_featL[o]);
    }
}

// ---------------- tf32 mma.sync GEMM, 3xTF32, 2-stage cp.async ----------------
// CTA tile 128(M) x 64(N), 8 warps as 4x2, warp tile 32x32. 3 CTAs/SM target.
__global__ __launch_bounds__(256, 3) void k_gemm_mma(
    const float* __restrict__ Ah, const float* __restrict__ Al,
    const float* __restrict__ Bh, const float* __restrict__ Bl,
    float* __restrict__ Cpart, int K, int N)
{
    extern __shared__ float smf[];
    const uint32_t sbase = smem_u32(smf);
    const int m0 = blockIdx.y * 128, n0 = blockIdx.x * 64;
    const int t = threadIdx.x, w = t >> 5, lane = t & 31;
    const int g = lane >> 2, c = lane & 3;
    const int wm = w >> 1, wn = w & 1;           // 4x2 warp grid, tile 32x32
    const int kbase = blockIdx.z * (K / KSPLIT);
    const int nch = (K / KSPLIT) / KC;
    float* C = Cpart + (size_t)blockIdx.z * MPAD * N;

    const float* srcA[2] = { Ah + (size_t)m0 * K, Al + (size_t)m0 * K };
    const float* srcB[2] = { Bh + (size_t)n0 * K, Bl + (size_t)n0 * K };

    auto issue = [&](int ch, int st) {
        int kb = kbase + ch * KC;
#pragma unroll
        for (int i = 0; i < 4; i++) {            // A: Ah,Al (512 f4 each pair)
            int idx = t + (i & 1) * 256;
            int mat = i >> 1;
            int row = idx >> 2, j4 = idx & 3;
            const float* src = srcA[mat] + (size_t)row * K + kb + j4 * 4;
            uint32_t dst = sbase + (uint32_t)((st * STAGEF + mat * MATOFF + row * SROW + j4 * 4) << 2);
            asm volatile("cp.async.cg.shared.global [%0], [%1], 16;" :: "r"(dst), "l"(src));
        }
#pragma unroll
        for (int i = 0; i < 2; i++) {            // B: Bh,Bl (256 f4 each)
            int idx = t + i * 256;
            int mat = idx >> 8;
            int row = (idx & 255) >> 2, j4 = idx & 3;
            const float* src = srcB[mat] + (size_t)row * K + kb + j4 * 4;
            uint32_t dst = sbase + (uint32_t)((st * STAGEF + BOFF + mat * BMAT + row * SROW + j4 * 4) << 2);
            asm volatile("cp.async.cg.shared.global [%0], [%1], 16;" :: "r"(dst), "l"(src));
        }
        CPA_COMMIT();
    };

    float acc[2][4][4];
#pragma unroll
    for (int mt = 0; mt < 2; mt++)
#pragma unroll
        for (int nt = 0; nt < 4; nt++)
#pragma unroll
            for (int e = 0; e < 4; e++) acc[mt][nt][e] = 0.f;

    const int aB = (wm * 32 + g) * 12 + c;       // float2 units
    const int bB = (wn * 32 + g) * 12 + c;

    issue(0, 0);
    issue(1, 1);

    for (int ch = 0; ch < nch; ch++) {
        CPA_WAIT1();
        __syncthreads();

        const float2* S2 = reinterpret_cast<const float2*>(smf + (ch & 1) * STAGEF);
#pragma unroll
        for (int kb2 = 0; kb2 < 8; kb2 += 4) {   // kb/2 in {0,4}
            uint32_t ah[2][4], al[2][4], bh[4][2], bl[4][2];
#pragma unroll
            for (int mt = 0; mt < 2; mt++) {
                float2 lo, hi;
                lo = S2[aB + mt * 192 + kb2];
                hi = S2[aB + mt * 192 + 96 + kb2];
                ah[mt][0] = __float_as_uint(lo.x); ah[mt][1] = __float_as_uint(hi.x);
                ah[mt][2] = __float_as_uint(lo.y); ah[mt][3] = __float_as_uint(hi.y);
                lo = S2[aB + 1536 + mt * 192 + kb2];     // Al = +MATOFF/2
                hi = S2[aB + 1536 + mt * 192 + 96 + kb2];
                al[mt][0] = __float_as_uint(lo.x); al[mt][1] = __float_as_uint(hi.x);
                al[mt][2] = __float_as_uint(lo.y); al[mt][3] = __float_as_uint(hi.y);
            }
#pragma unroll
            for (int nt = 0; nt < 4; nt++) {
                float2 vh = S2[bB + 3072 + nt * 96 + kb2];   // Bh = +BOFF/2
                float2 vl = S2[bB + 3840 + nt * 96 + kb2];   // Bl = +(BOFF+BMAT)/2
                bh[nt][0] = __float_as_uint(vh.x); bh[nt][1] = __float_as_uint(vh.y);
                bl[nt][0] = __float_as_uint(vl.x); bl[nt][1] = __float_as_uint(vl.y);
            }
#pragma unroll
            for (int mt = 0; mt < 2; mt++)
#pragma unroll
                for (int nt = 0; nt < 4; nt++)
                    MMA_TF32(acc[mt][nt], ah[mt], bh[nt]);
#pragma unroll
            for (int mt = 0; mt < 2; mt++)
#pragma unroll
                for (int nt = 0; nt < 4; nt++)
                    MMA_TF32(acc[mt][nt], ah[mt], bl[nt]);
#pragma unroll
            for (int mt = 0; mt < 2; mt++)
#pragma unroll
                for (int nt = 0; nt < 4; nt++)
                    MMA_TF32(acc[mt][nt], al[mt], bh[nt]);
        }
        __syncthreads();
        if (ch + 2 < nch) issue(ch + 2, ch & 1);
        else CPA_COMMIT();
    }

    // epilogue: raw fp32 partials
#pragma unroll
    for (int mt = 0; mt < 2; mt++) {
        int row0 = m0 + wm * 32 + mt * 16 + g;
#pragma unroll
        for (int nt = 0; nt < 4; nt++) {
            int col = n0 + wn * 32 + nt * 8 + 2 * c;
            *reinterpret_cast<float2*>(&C[(size_t)row0 * N + col])
                = make_float2(acc[mt][nt][0], acc[mt][nt][1]);
            *reinterpret_cast<float2*>(&C[(size_t)(row0 + 8) * N + col])
                = make_float2(acc[mt][nt][2], acc[mt][nt][3]);
        }
    }
}

// ---------------- reduce1: sum partials + bias -> split+interleaved convH/L ----------------
__global__ void k_reduce1(const float* __restrict__ bias) {
    int i = blockIdx.x * blockDim.x + threadIdx.x;
    if (i >= MPAD * (KCONV / 8)) return;
    size_t o = (size_t)i * 8;
    int n0 = (i & 127) * 8;
    float v[8];
    *reinterpret_cast<float4*>(v)     = *reinterpret_cast<const float4*>(&g_part[o]);
    *reinterpret_cast<float4*>(v + 4) = *reinterpret_cast<const float4*>(&g_part[o + 4]);
#pragma unroll
    for (int s = 1; s < KSPLIT; s++) {
        size_t so = (size_t)s * MPAD * KCONV + o;
        float4 a = *reinterpret_cast<const float4*>(&g_part[so]);
        float4 b = *reinterpret_cast<const float4*>(&g_part[so + 4]);
        v[0] += a.x; v[1] += a.y; v[2] += a.z; v[3] += a.w;
        v[4] += b.x; v[5] += b.y; v[6] += b.z; v[7] += b.w;
    }
    float4 b0 = *reinterpret_cast<const float4*>(&bias[n0]);
    float4 b1 = *reinterpret_cast<const float4*>(&bias[n0 + 4]);
    v[0] += b0.x; v[1] += b0.y; v[2] += b0.z; v[3] += b0.w;
    v[4] += b1.x; v[5] += b1.y; v[6] += b1.z; v[7] += b1.w;
    split8_store(v, &g_convH[o], &g_convL[o]);
}

// ---------------- assemble (inline K-split reduce of gemm2 partials) ----------------
__global__ void k_assemble(const float* __restrict__ anchd, float* __restrict__ out) {
    int row = blockIdx.x;
    int b = row / NEDGE, e = row % NEDGE;
    float* prop   = out + (size_t)b * NPROP * NPRED;
    float* scores = out + (size_t)NB * NPROP * NPRED + (size_t)NB * NPROP + (size_t)b * NPROP;
    const float* p0 = g_part + (size_t)row * NPAD;
    auto rcval = [&](int n) {
        float v = g_bc[n] + p0[n];
#pragma unroll
        for (int z = 1; z < KSPLIT; z++)
            v += p0[(size_t)z * MPAD * NPAD + n];
        return v;
    };
    for (int l = threadIdx.x; l < NANG * NPRED; l += blockDim.x) {
        int a = l / NPRED, q = l % NPRED;
        int p = e * NANG + a;
        float v;
        if (q < 2)      v = rcval(NREG + a * 2 + q);
        else if (q < 4) v = anchd[(size_t)p * NPRED + q];
        else            v = anchd[(size_t)p * NPRED + q] + rcval(a * 73 + (q - 4));
        prop[(size_t)p * NPRED + q] = v;
    }
    if (threadIdx.x < NANG) {
        int a = threadIdx.x;
        int p = e * NANG + a;
        float l0 = rcval(NREG + a * 2);
        float l1 = rcval(NREG + a * 2 + 1);
        scores[p] = 1.0f / (1.0f + expf(l0 - l1));
    }
}

// ---------------- NMS: stable descending argsort + sorted gather ----------------
__global__ void k_sort(const float* __restrict__ out) {
    int b = blockIdx.x;
    __shared__ float s[NPROP];
    const float* scores = out + (size_t)NB * NPROP * NPRED + (size_t)NB * NPROP + (size_t)b * NPROP;
    const float* prop   = out + (size_t)b * NPROP * NPRED;
    for (int i = threadIdx.x; i < NPROP; i += blockDim.x) s[i] = scores[i];
    __syncthreads();
    for (int i = threadIdx.x; i < NPROP; i += blockDim.x) {
        float si = s[i];
        int r = 0;
        for (int j = 0; j < NPROP; j++) {
            float sj = s[j];
            r += (sj > si) || (sj == si && j < i);
        }
        int base = b * NPROP + r;
        g_order[base] = i;
        float p2 = prop[(size_t)i * NPRED + 2];
        float p4 = prop[(size_t)i * NPRED + 4];
        float st = fminf(fmaxf(rintf(p2 * NSTRIPSF), 0.0f), NSTRIPSF);
        float en = fminf(fmaxf(st + p4 - 1.0f, 0.0f), NSTRIPSF);
        g_sstart[base] = st;
        g_send[base]   = en;
        float* dst = g_sxs + (size_t)base * NOFF;
        const float* src = prop + (size_t)i * NPRED + 5;
        for (int k = 0; k < NOFF; k++) dst[k] = src[k];
    }
}

// ---------------- NMS: pairwise suppression bitmatrix ----------------
__global__ void k_pairs() {
    int b    = blockIdx.y;
    int warp = threadIdx.x >> 5;
    int lane = threadIdx.x & 31;
    int i    = blockIdx.x * 8 + warp;
    if (i >= NPROP) return;
    int base = b * NPROP;
    float si = g_sstart[base + i], ei = g_send[base + i];
    const float* xi = g_sxs + (size_t)(base + i) * NOFF;
    for (int jw = 0; jw < NWORDS; jw++) {
        int j = jw * 32 + lane;
        bool sup = false;
        if (j < NPROP) {
            float s  = fmaxf(si, g_sstart[base + j]);
            float e  = fminf(ei, g_send[base + j]);
            float cnt = e - s + 1.0f;
            if (cnt > 0.0f) {
                const float* xj = g_sxs + (size_t)(base + j) * NOFF;
                int k0 = (int)s;
                int k1 = (int)floorf(e);
                float sum = 0.0f;
                for (int k = k0; k <= k1; k++) sum += fabsf(xi[k] - xj[k]);
                sup = (sum / fmaxf(cnt, 1.0f)) < NMS_T;
            }
        }
        unsigned m = __ballot_sync(0xFFFFFFFFu, sup);
        if (lane == 0) g_sup[(size_t)(base + i) * NWORDS + jw] = m;
    }
}

// ---------------- NMS: sequential scan, smem-staged ----------------
__global__ __launch_bounds__(256) void k_scan(float* __restrict__ out) {
    int b = blockIdx.x;
    __shared__ unsigned ssup[2][NCHUNK][NWORDS + 1];
    __shared__ int      sorder[NPROP];
    __shared__ float    skeep [NPROP];
    int t = threadIdx.x, lane = t & 31, warp = t >> 5;
    int base = b * NPROP;
    const unsigned* gs = g_sup + (size_t)base * NWORDS;

    for (int i = t; i < NPROP; i += 256) sorder[i] = g_order[base + i];
    for (int x = t; x < NCHUNK * NWORDS; x += 256)
        ssup[0][x / NWORDS][x % NWORDS] = gs[x];
    __syncthreads();

    unsigned my = 0;
    for (int c = 0; c < NCHUNKS; c++) {
        if (warp != 0) {
            if (c + 1 < NCHUNKS) {
                int i0 = (c + 1) * NCHUNK;
                int cnt = min(NCHUNK, NPROP - i0) * NWORDS;
                int tt = t - 32;
                for (int x = tt; x < cnt; x += 224)
                    ssup[(c + 1) & 1][x / NWORDS][x % NWORDS] = gs[(size_t)i0 * NWORDS + x];
            }
        } else {
            int i1 = min(NPROP, (c + 1) * NCHUNK);
            int lw = (lane < NWORDS) ? lane : 0;
            for (int i = c * NCHUNK; i < i1; i++) {
                unsigned row = ssup[c & 1][i - c * NCHUNK][lw];
                int wi = i >> 5, bit = i & 31;
                unsigned wsup = __shfl_sync(0xFFFFFFFFu, my, wi);
                bool kept = ((wsup >> bit) & 1u) == 0u;
                if (kept) {
                    unsigned m;
                    if (lane > wi)       m = 0xFFFFFFFFu;
                    else if (lane == wi) m = (bit == 31) ? 0u : (0xFFFFFFFFu << (bit + 1));
                    else                 m = 0u;
                    my |= row & m;
                }
                if (lane == 0) skeep[sorder[i]] = kept ? 1.0f : 0.0f;
            }
        }
        __syncthreads();
    }
    float* keep = out + (size_t)NB * NPROP * NPRED + (size_t)b * NPROP;
    for (int i = t; i < NPROP; i += 256) keep[i] = skeep[i];
}

// ---------------- launcher ----------------
#define GEMM_SMEM (2 * STAGEF * 4)   // 73728 bytes

extern "C" void kernel_launch(void* const* d_in, const int* in_sizes, int n_in,
                              void* d_out, int out_size) {
    const float* feat   = (const float*)d_in[0];
    const float* W_conv = (const float*)d_in[1];
    const float* b_conv = (const float*)d_in[2];
    const float* W_cls  = (const float*)d_in[3];
    const float* b_cls  = (const float*)d_in[4];
    const float* W_reg  = (const float*)d_in[5];
    const float* b_reg  = (const float*)d_in[6];
    const float* anchd  = (const float*)d_in[8];
    float* out = (float*)d_out;

    void *pFH, *pFL, *pWH, *pWL, *pCH, *pCL, *pWcH, *pWcL, *pPart;
    cudaGetSymbolAddress(&pFH,  g_featH);
    cudaGetSymbolAddress(&pFL,  g_featL);
    cudaGetSymbolAddress(&pWH,  g_WconvH);
    cudaGetSymbolAddress(&pWL,  g_WconvL);
    cudaGetSymbolAddress(&pCH,  g_convH);
    cudaGetSymbolAddress(&pCL,  g_convL);
    cudaGetSymbolAddress(&pWcH, g_WcH);
    cudaGetSymbolAddress(&pWcL, g_WcL);
    cudaGetSymbolAddress(&pPart, g_part);

    cudaFuncSetAttribute(k_gemm_mma, cudaFuncAttributeMaxDynamicSharedMemorySize, GEMM_SMEM);

    k_prep<<<(PREP_TOTAL + 255) / 256, 256>>>(W_reg, b_reg, W_cls, b_cls, W_conv, feat);

    // GEMM1: feat(1408x512) @ W_conv^T -> partials -> convH/L
    k_gemm_mma<<<dim3(KCONV / 64, MPAD / 128, KSPLIT), 256, GEMM_SMEM>>>(
        (const float*)pFH, (const float*)pFL, (const float*)pWH, (const float*)pWL,
        (float*)pPart, KBACK, KCONV);
    k_reduce1<<<(MPAD * (KCONV / 8) + 255) / 256, 256>>>(b_conv);

    // GEMM2: conv(1408x1024) @ Wc^T -> partials (reduced inline by assemble)
    k_gemm_mma<<<dim3(NPAD / 64, MPAD / 128, KSPLIT), 256, GEMM_SMEM>>>(
        (const float*)pCH, (const float*)pCL, (const float*)pWcH, (const float*)pWcL,
        (float*)pPart, KCONV, NPAD);

    k_assemble<<<MROWS, 256>>>(anchd, out);
    k_sort<<<NB, 256>>>(out);
    k_pairs<<<dim3((NPROP + 7) / 8, NB), 256>>>();
    k_scan<<<NB, 256>>>(out);
}

// round 13
// speedup vs baseline: 1.3437x; 1.1826x over previous
#include <cuda_runtime.h>
#include <cuda_fp16.h>
#include <math.h>
#include <stdint.h>

// ---------------- problem constants ----------------
#define NB      32
#define FH      11
#define FW      20
#define NEDGE   42
#define NANG    17
#define NPRED   77
#define NPROP   714
#define NOFF    72
#define KBACK   512
#define KCONV   1024
#define NREG    1241
#define NCLS    34
#define NPAD    1280
#define MROWS   1344
#define MPAD    1408
#define NWORDS  23
#define NSTRIPSF 71.0f
#define NMS_T   15.0f
#define NCHUNK  128
#define NCHUNKS 6
#define KC      32          // K per pipeline chunk (2 k16 mma groups)
#define KSPLIT  2
#define BSCALE  64.0f       // B pre-scale (exact pow2) to keep fp16 lo-parts normal
#define BINV    (1.0f / 64.0f)
// smem (uint32 word units): row stride 24 words; A 128 rows, B 64 rows; h+l each
#define A_SZW   3072        // 128 * 24
#define B_SZW   1536        // 64 * 24
#define STAGEW  9216        // 2*A_SZW + 2*B_SZW
#define GEMM_SMEM (2 * STAGEW * 4)   // 73728 bytes

// prep partition (16-float groups)
#define PREP_W  (NPAD * (KCONV / 16))    // 81920
#define PREP_S  (KCONV * (KBACK / 16))   // 32768
#define PREP_G  (MROWS * (KBACK / 16))   // 43008
#define PREP_TOTAL (PREP_W + PREP_S + PREP_G)

// ---------------- scratch (fp16 operands stored as packed uint32 pair-words) ----------------
__device__ __align__(16) unsigned g_featH16 [MPAD * KBACK / 2];
__device__ __align__(16) unsigned g_featL16 [MPAD * KBACK / 2];
__device__ __align__(16) unsigned g_WconvH16[KCONV * KBACK / 2];
__device__ __align__(16) unsigned g_WconvL16[KCONV * KBACK / 2];
__device__ __align__(16) unsigned g_convH16 [MPAD * KCONV / 2];
__device__ __align__(16) unsigned g_convL16 [MPAD * KCONV / 2];
__device__ __align__(16) unsigned g_WcH16   [NPAD * KCONV / 2];
__device__ __align__(16) unsigned g_WcL16   [NPAD * KCONV / 2];
__device__ float    g_bc    [NPAD];
__device__ float    g_part  [KSPLIT * MPAD * NPAD];
__device__ int      g_order [NB * NPROP];
__device__ float    g_sstart[NB * NPROP];
__device__ float    g_send  [NB * NPROP];
__device__ float    g_sxs   [NB * NPROP * NOFF];
__device__ unsigned g_sup   [NB * NPROP * NWORDS];

// ---------------- helpers ----------------
__device__ __forceinline__ unsigned pack2h(float x0, float x1) {
    __half h0 = __float2half_rn(x0), h1 = __float2half_rn(x1);
    return (unsigned)__half_as_ushort(h0) | ((unsigned)__half_as_ushort(h1) << 16);
}
// split 16 floats (scaled by s) into fp16 hi/lo pair-words, store interleaved 0,4,1,5,2,6,3,7
__device__ __forceinline__ void split16h_store(const float* v, float s,
                                               unsigned* H, unsigned* L) {
    unsigned hw[8], lw[8];
#pragma unroll
    for (int p = 0; p < 8; p++) {
        float x0 = v[2 * p] * s, x1 = v[2 * p + 1] * s;
        __half h0 = __float2half_rn(x0), h1 = __float2half_rn(x1);
        float l0 = x0 - __half2float(h0), l1 = x1 - __half2float(h1);
        hw[p] = (unsigned)__half_as_ushort(h0) | ((unsigned)__half_as_ushort(h1) << 16);
        lw[p] = pack2h(l0, l1);
    }
    *reinterpret_cast<uint4*>(H)     = make_uint4(hw[0], hw[4], hw[1], hw[5]);
    *reinterpret_cast<uint4*>(H + 4) = make_uint4(hw[2], hw[6], hw[3], hw[7]);
    *reinterpret_cast<uint4*>(L)     = make_uint4(lw[0], lw[4], lw[1], lw[5]);
    *reinterpret_cast<uint4*>(L + 4) = make_uint4(lw[2], lw[6], lw[3], lw[7]);
}
__device__ __forceinline__ uint32_t smem_u32(const void* p) {
    uint32_t a;
    asm("{ .reg .u64 tmp; cvta.to.shared.u64 tmp, %1; cvt.u32.u64 %0, tmp; }"
        : "=r"(a) : "l"(p));
    return a;
}
#define MMA_F16(d, a0, a1, a2, a3, b0, b1)                                       \
    asm volatile("mma.sync.aligned.m16n8k16.row.col.f32.f16.f16.f32 "            \
        "{%0,%1,%2,%3}, {%4,%5,%6,%7}, {%8,%9}, {%0,%1,%2,%3};"                  \
        : "+f"((d)[0]), "+f"((d)[1]), "+f"((d)[2]), "+f"((d)[3])                 \
        : "r"(a0), "r"(a1), "r"(a2), "r"(a3), "r"(b0), "r"(b1))
#define CPA_COMMIT() asm volatile("cp.async.commit_group;" ::: "memory")
#define CPA_WAIT1()  asm volatile("cp.async.wait_group 1;" ::: "memory")

// ---------------- fused prep: pack Wc(x64) + split Wconv(x64) + gather feat ----------------
__global__ void k_prep(const float* __restrict__ Wr, const float* __restrict__ br,
                       const float* __restrict__ Wc, const float* __restrict__ bc,
                       const float* __restrict__ Wconv, const float* __restrict__ feat) {
    int i = blockIdx.x * blockDim.x + threadIdx.x;
    if (i < PREP_W) {
        int row = i >> 6, k0 = (i & 63) * 16;
        float v[16];
#pragma unroll
        for (int q = 0; q < 16; q++) v[q] = 0.f;
        if (row < NREG) {
#pragma unroll
            for (int q = 0; q < 4; q++)
                *reinterpret_cast<float4*>(v + q * 4) =
                    *reinterpret_cast<const float4*>(&Wr[(size_t)row * KCONV + k0 + q * 4]);
        } else if (row < NREG + NCLS) {
#pragma unroll
            for (int q = 0; q < 4; q++)
                *reinterpret_cast<float4*>(v + q * 4) =
                    *reinterpret_cast<const float4*>(&Wc[(size_t)(row - NREG) * KCONV + k0 + q * 4]);
        }
        size_t o = ((size_t)row * KCONV + k0) >> 1;
        split16h_store(v, BSCALE, &g_WcH16[o], &g_WcL16[o]);
        if (i < NPAD) {
            float b = 0.f;
            if (i < NREG)             b = br[i];
            else if (i < NREG + NCLS) b = bc[i - NREG];
            g_bc[i] = b;
        }
        return;
    }
    i -= PREP_W;
    if (i < PREP_S) {
        size_t o = (size_t)i * 16;
        float v[16];
#pragma unroll
        for (int q = 0; q < 4; q++)
            *reinterpret_cast<float4*>(v + q * 4) =
                *reinterpret_cast<const float4*>(&Wconv[o + q * 4]);
        split16h_store(v, BSCALE, &g_WconvH16[o >> 1], &g_WconvL16[o >> 1]);
        return;
    }
    i -= PREP_S;
    if (i < PREP_G) {
        int m = i >> 5, c0 = (i & 31) * 16;
        int b = m / NEDGE, e = m % NEDGE;
        int h, w;
        if (e < FH)        { h = e;      w = 0;        }
        else if (e < 2*FH) { h = e - FH; w = FW - 1;   }
        else               { h = FH - 1; w = e - 2*FH; }
        float v[16];
#pragma unroll
        for (int j = 0; j < 16; j++)
            v[j] = feat[((size_t)(b * KBACK + c0 + j) * FH + h) * FW + w];
        size_t o = ((size_t)m * KBACK + c0) >> 1;
        split16h_store(v, 1.0f, &g_featH16[o], &g_featL16[o]);
    }
}

// ---------------- fp16 mma.sync GEMM, 3-term split, 2-stage cp.async ----------------
// CTA tile 128(M) x 64(N), 8 warps 4x2, warp tile 32x32, KC=32 (2 k16 groups).
// Operands are fp16 pair-words, interleaved per 16-k group. Acc = 64 x true value.
__global__ __launch_bounds__(256, 3) void k_gemm_f16(
    const unsigned* __restrict__ Ah, const unsigned* __restrict__ Al,
    const unsigned* __restrict__ Bh, const unsigned* __restrict__ Bl,
    float* __restrict__ Cpart, int K, int N)   // K in elements (halves per row)
{
    extern __shared__ unsigned smw[];
    const uint32_t sbase = smem_u32(smw);
    const int m0 = blockIdx.y * 128, n0 = blockIdx.x * 64;
    const int t = threadIdx.x, w = t >> 5, lane = t & 31;
    const int g = lane >> 2, c = lane & 3;
    const int wm = w >> 1, wn = w & 1;
    const int Kw = K >> 1;                      // row stride in words
    const int kbase = blockIdx.z * (K / KSPLIT);
    const int nch = (K / KSPLIT) / KC;
    float* C = Cpart + (size_t)blockIdx.z * MPAD * N;

    const unsigned* srcA[2] = { Ah + (size_t)m0 * Kw, Al + (size_t)m0 * Kw };
    const unsigned* srcB[2] = { Bh + (size_t)n0 * Kw, Bl + (size_t)n0 * Kw };

    auto issue = [&](int ch, int st) {
        int kbw = (kbase + ch * KC) >> 1;       // word offset within row
#pragma unroll
        for (int i = 0; i < 4; i++) {           // A: Ah,Al — 512 x 16B each mat pair
            int idx = t + (i & 1) * 256;
            int mat = i >> 1;
            int row = idx >> 2, q = idx & 3;
            const unsigned* src = srcA[mat] + (size_t)row * Kw + kbw + q * 4;
            uint32_t dst = sbase + (uint32_t)((st * STAGEW + mat * A_SZW + row * 24 + q * 4) << 2);
            asm volatile("cp.async.cg.shared.global [%0], [%1], 16;" :: "r"(dst), "l"(src));
        }
#pragma unroll
        for (int i = 0; i < 2; i++) {           // B: Bh,Bl — 256 x 16B each
            int mat = i;
            int row = t >> 2, q = t & 3;
            const unsigned* src = srcB[mat] + (size_t)row * Kw + kbw + q * 4;
            uint32_t dst = sbase + (uint32_t)((st * STAGEW + 2 * A_SZW + mat * B_SZW + row * 24 + q * 4) << 2);
            asm volatile("cp.async.cg.shared.global [%0], [%1], 16;" :: "r"(dst), "l"(src));
        }
        CPA_COMMIT();
    };

    float acc[2][4][4];
#pragma unroll
    for (int mt = 0; mt < 2; mt++)
#pragma unroll
        for (int nt = 0; nt < 4; nt++)
#pragma unroll
            for (int e = 0; e < 4; e++) acc[mt][nt][e] = 0.f;

    issue(0, 0);
    issue(1, 1);

    for (int ch = 0; ch < nch; ch++) {
        CPA_WAIT1();
        __syncthreads();
        const unsigned* SW = smw + (ch & 1) * STAGEW;
#pragma unroll
        for (int grp = 0; grp < 2; grp++) {
            const int go = grp * 8 + 2 * c;
            // A fragments: (a0,a2) from row g, (a1,a3) from row g+8; h and l
            unsigned ahf[2][4], alf[2][4];
#pragma unroll
            for (int mt = 0; mt < 2; mt++) {
                int r = (wm * 32 + mt * 16 + g) * 24 + go;
                uint2 x0 = *reinterpret_cast<const uint2*>(&SW[r]);
                uint2 x1 = *reinterpret_cast<const uint2*>(&SW[r + 192]);        // +8 rows
                ahf[mt][0] = x0.x; ahf[mt][1] = x1.x; ahf[mt][2] = x0.y; ahf[mt][3] = x1.y;
                uint2 y0 = *reinterpret_cast<const uint2*>(&SW[r + A_SZW]);
                uint2 y1 = *reinterpret_cast<const uint2*>(&SW[r + A_SZW + 192]);
                alf[mt][0] = y0.x; alf[mt][1] = y1.x; alf[mt][2] = y0.y; alf[mt][3] = y1.y;
            }
            uint2 bhf[4], blf[4];
#pragma unroll
            for (int nt = 0; nt < 4; nt++) {
                int n = (wn * 32 + nt * 8 + g) * 24 + go;
                bhf[nt] = *reinterpret_cast<const uint2*>(&SW[2 * A_SZW + n]);
                blf[nt] = *reinterpret_cast<const uint2*>(&SW[2 * A_SZW + B_SZW + n]);
            }
            // term-major (RAW distance 8)
#pragma unroll
            for (int mt = 0; mt < 2; mt++)
#pragma unroll
                for (int nt = 0; nt < 4; nt++)
                    MMA_F16(acc[mt][nt], ahf[mt][0], ahf[mt][1], ahf[mt][2], ahf[mt][3],
                            bhf[nt].x, bhf[nt].y);
#pragma unroll
            for (int mt = 0; mt < 2; mt++)
#pragma unroll
                for (int nt = 0; nt < 4; nt++)
                    MMA_F16(acc[mt][nt], ahf[mt][0], ahf[mt][1], ahf[mt][2], ahf[mt][3],
                            blf[nt].x, blf[nt].y);
#pragma unroll
            for (int mt = 0; mt < 2; mt++)
#pragma unroll
                for (int nt = 0; nt < 4; nt++)
                    MMA_F16(acc[mt][nt], alf[mt][0], alf[mt][1], alf[mt][2], alf[mt][3],
                            bhf[nt].x, bhf[nt].y);
        }
        __syncthreads();
        if (ch + 2 < nch) issue(ch + 2, ch & 1);
        else CPA_COMMIT();
    }

    // epilogue: raw fp32 partials (still scaled by BSCALE; descale downstream)
#pragma unroll
    for (int mt = 0; mt < 2; mt++) {
        int row0 = m0 + wm * 32 + mt * 16 + g;
#pragma unroll
        for (int nt = 0; nt < 4; nt++) {
            int col = n0 + wn * 32 + nt * 8 + 2 * c;
            *reinterpret_cast<float2*>(&C[(size_t)row0 * N + col])
                = make_float2(acc[mt][nt][0], acc[mt][nt][1]);
            *reinterpret_cast<float2*>(&C[(size_t)(row0 + 8) * N + col])
                = make_float2(acc[mt][nt][2], acc[mt][nt][3]);
        }
    }
}

// ---------------- reduce1: (sum partials)/64 + bias -> fp16 split conv ----------------
__global__ void k_reduce1(const float* __restrict__ bias) {
    int i = blockIdx.x * blockDim.x + threadIdx.x;
    if (i >= MPAD * (KCONV / 16)) return;
    size_t o = (size_t)i * 16;
    int n0 = (i & 63) * 16;
    float v[16];
#pragma unroll
    for (int q = 0; q < 4; q++) {
        float4 a = *reinterpret_cast<const float4*>(&g_part[o + q * 4]);
        float4 b = *reinterpret_cast<const float4*>(&g_part[(size_t)MPAD * KCONV + o + q * 4]);
        float4 bv = *reinterpret_cast<const float4*>(&bias[n0 + q * 4]);
        v[q * 4 + 0] = (a.x + b.x) * BINV + bv.x;
        v[q * 4 + 1] = (a.y + b.y) * BINV + bv.y;
        v[q * 4 + 2] = (a.z + b.z) * BINV + bv.z;
        v[q * 4 + 3] = (a.w + b.w) * BINV + bv.w;
    }
    split16h_store(v, 1.0f, &g_convH16[o >> 1], &g_convL16[o >> 1]);
}

// ---------------- assemble (inline K-split reduce + descale of gemm2 partials) ----------------
__global__ void k_assemble(const float* __restrict__ anchd, float* __restrict__ out) {
    int row = blockIdx.x;
    int b = row / NEDGE, e = row % NEDGE;
    float* prop   = out + (size_t)b * NPROP * NPRED;
    float* scores = out + (size_t)NB * NPROP * NPRED + (size_t)NB * NPROP + (size_t)b * NPROP;
    const float* p0 = g_part + (size_t)row * NPAD;
    auto rcval = [&](int n) {
        float v = p0[n] + p0[(size_t)MPAD * NPAD + n];
        return v * BINV + g_bc[n];
    };
    for (int l = threadIdx.x; l < NANG * NPRED; l += blockDim.x) {
        int a = l / NPRED, q = l % NPRED;
        int p = e * NANG + a;
        float v;
        if (q < 2)      v = rcval(NREG + a * 2 + q);
        else if (q < 4) v = anchd[(size_t)p * NPRED + q];
        else            v = anchd[(size_t)p * NPRED + q] + rcval(a * 73 + (q - 4));
        prop[(size_t)p * NPRED + q] = v;
    }
    if (threadIdx.x < NANG) {
        int a = threadIdx.x;
        int p = e * NANG + a;
        float l0 = rcval(NREG + a * 2);
        float l1 = rcval(NREG + a * 2 + 1);
        scores[p] = 1.0f / (1.0f + expf(l0 - l1));
    }
}

// ---------------- NMS: stable descending argsort + sorted gather ----------------
__global__ void k_sort(const float* __restrict__ out) {
    int b = blockIdx.x;
    __shared__ float s[NPROP];
    const float* scores = out + (size_t)NB * NPROP * NPRED + (size_t)NB * NPROP + (size_t)b * NPROP;
    const float* prop   = out + (size_t)b * NPROP * NPRED;
    for (int i = threadIdx.x; i < NPROP; i += blockDim.x) s[i] = scores[i];
    __syncthreads();
    for (int i = threadIdx.x; i < NPROP; i += blockDim.x) {
        float si = s[i];
        int r = 0;
        for (int j = 0; j < NPROP; j++) {
            float sj = s[j];
            r += (sj > si) || (sj == si && j < i);
        }
        int base = b * NPROP + r;
        g_order[base] = i;
        float p2 = prop[(size_t)i * NPRED + 2];
        float p4 = prop[(size_t)i * NPRED + 4];
        float st = fminf(fmaxf(rintf(p2 * NSTRIPSF), 0.0f), NSTRIPSF);
        float en = fminf(fmaxf(st + p4 - 1.0f, 0.0f), NSTRIPSF);
        g_sstart[base] = st;
        g_send[base]   = en;
        float* dst = g_sxs + (size_t)base * NOFF;
        const float* src = prop + (size_t)i * NPRED + 5;
        for (int k = 0; k < NOFF; k++) dst[k] = src[k];
    }
}

// ---------------- NMS: pairwise suppression bitmatrix ----------------
__global__ void k_pairs() {
    int b    = blockIdx.y;
    int warp = threadIdx.x >> 5;
    int lane = threadIdx.x & 31;
    int i    = blockIdx.x * 8 + warp;
    if (i >= NPROP) return;
    int base = b * NPROP;
    float si = g_sstart[base + i], ei = g_send[base + i];
    const float* xi = g_sxs + (size_t)(base + i) * NOFF;
    for (int jw = 0; jw < NWORDS; jw++) {
        int j = jw * 32 + lane;
        bool sup = false;
        if (j < NPROP) {
            float s  = fmaxf(si, g_sstart[base + j]);
            float e  = fminf(ei, g_send[base + j]);
            float cnt = e - s + 1.0f;
            if (cnt > 0.0f) {
                const float* xj = g_sxs + (size_t)(base + j) * NOFF;
                int k0 = (int)s;
                int k1 = (int)floorf(e);
                float sum = 0.0f;
                for (int k = k0; k <= k1; k++) sum += fabsf(xi[k] - xj[k]);
                sup = (sum / fmaxf(cnt, 1.0f)) < NMS_T;
            }
        }
        unsigned m = __ballot_sync(0xFFFFFFFFu, sup);
        if (lane == 0) g_sup[(size_t)(base + i) * NWORDS + jw] = m;
    }
}

// ---------------- NMS: sequential scan, smem-staged ----------------
__global__ __launch_bounds__(256) void k_scan(float* __restrict__ out) {
    int b = blockIdx.x;
    __shared__ unsigned ssup[2][NCHUNK][NWORDS + 1];
    __shared__ int      sorder[NPROP];
    __shared__ float    skeep [NPROP];
    int t = threadIdx.x, lane = t & 31, warp = t >> 5;
    int base = b * NPROP;
    const unsigned* gs = g_sup + (size_t)base * NWORDS;

    for (int i = t; i < NPROP; i += 256) sorder[i] = g_order[base + i];
    for (int x = t; x < NCHUNK * NWORDS; x += 256)
        ssup[0][x / NWORDS][x % NWORDS] = gs[x];
    __syncthreads();

    unsigned my = 0;
    for (int c = 0; c < NCHUNKS; c++) {
        if (warp != 0) {
            if (c + 1 < NCHUNKS) {
                int i0 = (c + 1) * NCHUNK;
                int cnt = min(NCHUNK, NPROP - i0) * NWORDS;
                int tt = t - 32;
                for (int x = tt; x < cnt; x += 224)
                    ssup[(c + 1) & 1][x / NWORDS][x % NWORDS] = gs[(size_t)i0 * NWORDS + x];
            }
        } else {
            int i1 = min(NPROP, (c + 1) * NCHUNK);
            int lw = (lane < NWORDS) ? lane : 0;
            for (int i = c * NCHUNK; i < i1; i++) {
                unsigned row = ssup[c & 1][i - c * NCHUNK][lw];
                int wi = i >> 5, bit = i & 31;
                unsigned wsup = __shfl_sync(0xFFFFFFFFu, my, wi);
                bool kept = ((wsup >> bit) & 1u) == 0u;
                if (kept) {
                    unsigned m;
                    if (lane > wi)       m = 0xFFFFFFFFu;
                    else if (lane == wi) m = (bit == 31) ? 0u : (0xFFFFFFFFu << (bit + 1));
                    else                 m = 0u;
                    my |= row & m;
                }
                if (lane == 0) skeep[sorder[i]] = kept ? 1.0f : 0.0f;
            }
        }
        __syncthreads();
    }
    float* keep = out + (size_t)NB * NPROP * NPRED + (size_t)b * NPROP;
    for (int i = t; i < NPROP; i += 256) keep[i] = skeep[i];
}

// ---------------- launcher ----------------
extern "C" void kernel_launch(void* const* d_in, const int* in_sizes, int n_in,
                              void* d_out, int out_size) {
    const float* feat   = (const float*)d_in[0];
    const float* W_conv = (const float*)d_in[1];
    const float* b_conv = (const float*)d_in[2];
    const float* W_cls  = (const float*)d_in[3];
    const float* b_cls  = (const float*)d_in[4];
    const float* W_reg  = (const float*)d_in[5];
    const float* b_reg  = (const float*)d_in[6];
    const float* anchd  = (const float*)d_in[8];
    float* out = (float*)d_out;

    void *pFH, *pFL, *pWH, *pWL, *pCH, *pCL, *pWcH, *pWcL, *pPart;
    cudaGetSymbolAddress(&pFH,  g_featH16);
    cudaGetSymbolAddress(&pFL,  g_featL16);
    cudaGetSymbolAddress(&pWH,  g_WconvH16);
    cudaGetSymbolAddress(&pWL,  g_WconvL16);
    cudaGetSymbolAddress(&pCH,  g_convH16);
    cudaGetSymbolAddress(&pCL,  g_convL16);
    cudaGetSymbolAddress(&pWcH, g_WcH16);
    cudaGetSymbolAddress(&pWcL, g_WcL16);
    cudaGetSymbolAddress(&pPart, g_part);

    cudaFuncSetAttribute(k_gemm_f16, cudaFuncAttributeMaxDynamicSharedMemorySize, GEMM_SMEM);

    k_prep<<<(PREP_TOTAL + 255) / 256, 256>>>(W_reg, b_reg, W_cls, b_cls, W_conv, feat);

    // GEMM1: feat(1408x512) @ (64*W_conv)^T -> partials -> conv fp16 h/l
    k_gemm_f16<<<dim3(KCONV / 64, MPAD / 128, KSPLIT), 256, GEMM_SMEM>>>(
        (const unsigned*)pFH, (const unsigned*)pFL,
        (const unsigned*)pWH, (const unsigned*)pWL,
        (float*)pPart, KBACK, KCONV);
    k_reduce1<<<(MPAD * (KCONV / 16) + 255) / 256, 256>>>(b_conv);

    // GEMM2: conv(1408x1024) @ (64*Wc)^T -> partials (reduced + descaled in assemble)
    k_gemm_f16<<<dim3(NPAD / 64, MPAD / 128, KSPLIT), 256, GEMM_SMEM>>>(
        (const unsigned*)pCH, (const unsigned*)pCL,
        (const unsigned*)pWcH, (const unsigned*)pWcL,
        (float*)pPart, KCONV, NPAD);

    k_assemble<<<MROWS, 256>>>(anchd, out);
    k_sort<<<NB, 256>>>(out);
    k_pairs<<<dim3((NPROP + 7) / 8, NB), 256>>>();
    k_scan<<<NB, 256>>>(out);
}

// round 14
// speedup vs baseline: 1.4499x; 1.0791x over previous
#include <cuda_runtime.h>
#include <cuda_fp16.h>
#include <math.h>
#include <stdint.h>

// ---------------- problem constants ----------------
#define NB      32
#define FH      11
#define FW      20
#define NEDGE   42
#define NANG    17
#define NPRED   77
#define NPROP   714
#define NOFF    72
#define KBACK   512
#define KCONV   1024
#define NREG    1241
#define NCLS    34
#define NPAD    1280
#define MROWS   1344
#define MPAD    1408
#define NWORDS  23
#define NSTRIPSF 71.0f
#define NMS_T   15.0f
#define NCHUNK  128
#define NCHUNKS 6
#define KC      32          // K per pipeline chunk (2 k16 mma groups)
#define KSPLIT  2
#define BSCALE  64.0f       // B pre-scale (exact pow2) to keep fp16 lo-parts normal
#define BINV    (1.0f / 64.0f)
// smem (uint32 word units): row stride 24 words; A 128 rows, B 64 rows; h+l each
#define A_SZW   3072        // 128 * 24
#define B_SZW   1536        // 64 * 24
#define STAGEW  9216        // 2*A_SZW + 2*B_SZW
#define GEMM_SMEM (2 * STAGEW * 4)   // 73728 bytes

// prep partition (16-float groups)
#define PREP_W  (NPAD * (KCONV / 16))    // 81920
#define PREP_S  (KCONV * (KBACK / 16))   // 32768
#define PREP_G  (MROWS * (KBACK / 16))   // 43008
#define PREP_TOTAL (PREP_W + PREP_S + PREP_G)

// ---------------- scratch ----------------
__device__ __align__(16) unsigned g_featH16 [MPAD * KBACK / 2];
__device__ __align__(16) unsigned g_featL16 [MPAD * KBACK / 2];
__device__ __align__(16) unsigned g_WconvH16[KCONV * KBACK / 2];
__device__ __align__(16) unsigned g_WconvL16[KCONV * KBACK / 2];
__device__ __align__(16) unsigned g_convH16 [MPAD * KCONV / 2];
__device__ __align__(16) unsigned g_convL16 [MPAD * KCONV / 2];
__device__ __align__(16) unsigned g_WcH16   [NPAD * KCONV / 2];
__device__ __align__(16) unsigned g_WcL16   [NPAD * KCONV / 2];
__device__ float    g_bc    [NPAD];
__device__ float    g_part  [KSPLIT * MPAD * NPAD];
__device__ int      g_order [NB * NPROP];
__device__ float    g_sstart[NB * NPROP];
__device__ float    g_send  [NB * NPROP];
__device__ float    g_sxsT  [NB * NOFF * NPROP];   // strip-major: [b][k][prop]
__device__ unsigned g_sup   [NB * NPROP * NWORDS];

// ---------------- helpers ----------------
__device__ __forceinline__ unsigned pack2h(float x0, float x1) {
    __half h0 = __float2half_rn(x0), h1 = __float2half_rn(x1);
    return (unsigned)__half_as_ushort(h0) | ((unsigned)__half_as_ushort(h1) << 16);
}
__device__ __forceinline__ void split16h_store(const float* v, float s,
                                               unsigned* H, unsigned* L) {
    unsigned hw[8], lw[8];
#pragma unroll
    for (int p = 0; p < 8; p++) {
        float x0 = v[2 * p] * s, x1 = v[2 * p + 1] * s;
        __half h0 = __float2half_rn(x0), h1 = __float2half_rn(x1);
        float l0 = x0 - __half2float(h0), l1 = x1 - __half2float(h1);
        hw[p] = (unsigned)__half_as_ushort(h0) | ((unsigned)__half_as_ushort(h1) << 16);
        lw[p] = pack2h(l0, l1);
    }
    *reinterpret_cast<uint4*>(H)     = make_uint4(hw[0], hw[4], hw[1], hw[5]);
    *reinterpret_cast<uint4*>(H + 4) = make_uint4(hw[2], hw[6], hw[3], hw[7]);
    *reinterpret_cast<uint4*>(L)     = make_uint4(lw[0], lw[4], lw[1], lw[5]);
    *reinterpret_cast<uint4*>(L + 4) = make_uint4(lw[2], lw[6], lw[3], lw[7]);
}
__device__ __forceinline__ uint32_t smem_u32(const void* p) {
    uint32_t a;
    asm("{ .reg .u64 tmp; cvta.to.shared.u64 tmp, %1; cvt.u32.u64 %0, tmp; }"
        : "=r"(a) : "l"(p));
    return a;
}
#define MMA_F16(d, a0, a1, a2, a3, b0, b1)                                       \
    asm volatile("mma.sync.aligned.m16n8k16.row.col.f32.f16.f16.f32 "            \
        "{%0,%1,%2,%3}, {%4,%5,%6,%7}, {%8,%9}, {%0,%1,%2,%3};"                  \
        : "+f"((d)[0]), "+f"((d)[1]), "+f"((d)[2]), "+f"((d)[3])                 \
        : "r"(a0), "r"(a1), "r"(a2), "r"(a3), "r"(b0), "r"(b1))
#define CPA_COMMIT() asm volatile("cp.async.commit_group;" ::: "memory")
#define CPA_WAIT1()  asm volatile("cp.async.wait_group 1;" ::: "memory")

// ---------------- fused prep ----------------
__global__ void k_prep(const float* __restrict__ Wr, const float* __restrict__ br,
                       const float* __restrict__ Wc, const float* __restrict__ bc,
                       const float* __restrict__ Wconv, const float* __restrict__ feat) {
    int i = blockIdx.x * blockDim.x + threadIdx.x;
    if (i < PREP_W) {
        int row = i >> 6, k0 = (i & 63) * 16;
        float v[16];
#pragma unroll
        for (int q = 0; q < 16; q++) v[q] = 0.f;
        if (row < NREG) {
#pragma unroll
            for (int q = 0; q < 4; q++)
                *reinterpret_cast<float4*>(v + q * 4) =
                    *reinterpret_cast<const float4*>(&Wr[(size_t)row * KCONV + k0 + q * 4]);
        } else if (row < NREG + NCLS) {
#pragma unroll
            for (int q = 0; q < 4; q++)
                *reinterpret_cast<float4*>(v + q * 4) =
                    *reinterpret_cast<const float4*>(&Wc[(size_t)(row - NREG) * KCONV + k0 + q * 4]);
        }
        size_t o = ((size_t)row * KCONV + k0) >> 1;
        split16h_store(v, BSCALE, &g_WcH16[o], &g_WcL16[o]);
        if (i < NPAD) {
            float b = 0.f;
            if (i < NREG)             b = br[i];
            else if (i < NREG + NCLS) b = bc[i - NREG];
            g_bc[i] = b;
        }
        return;
    }
    i -= PREP_W;
    if (i < PREP_S) {
        size_t o = (size_t)i * 16;
        float v[16];
#pragma unroll
        for (int q = 0; q < 4; q++)
            *reinterpret_cast<float4*>(v + q * 4) =
                *reinterpret_cast<const float4*>(&Wconv[o + q * 4]);
        split16h_store(v, BSCALE, &g_WconvH16[o >> 1], &g_WconvL16[o >> 1]);
        return;
    }
    i -= PREP_S;
    if (i < PREP_G) {
        int m = i >> 5, c0 = (i & 31) * 16;
        int b = m / NEDGE, e = m % NEDGE;
        int h, w;
        if (e < FH)        { h = e;      w = 0;        }
        else if (e < 2*FH) { h = e - FH; w = FW - 1;   }
        else               { h = FH - 1; w = e - 2*FH; }
        float v[16];
#pragma unroll
        for (int j = 0; j < 16; j++)
            v[j] = feat[((size_t)(b * KBACK + c0 + j) * FH + h) * FW + w];
        size_t o = ((size_t)m * KBACK + c0) >> 1;
        split16h_store(v, 1.0f, &g_featH16[o], &g_featL16[o]);
    }
}

// ---------------- fp16 mma.sync GEMM, 3-term split, 2-stage cp.async ----------------
__global__ __launch_bounds__(256, 3) void k_gemm_f16(
    const unsigned* __restrict__ Ah, const unsigned* __restrict__ Al,
    const unsigned* __restrict__ Bh, const unsigned* __restrict__ Bl,
    float* __restrict__ Cpart, int K, int N)
{
    extern __shared__ unsigned smw[];
    const uint32_t sbase = smem_u32(smw);
    const int m0 = blockIdx.y * 128, n0 = blockIdx.x * 64;
    const int t = threadIdx.x, w = t >> 5, lane = t & 31;
    const int g = lane >> 2, c = lane & 3;
    const int wm = w >> 1, wn = w & 1;
    const int Kw = K >> 1;
    const int kbase = blockIdx.z * (K / KSPLIT);
    const int nch = (K / KSPLIT) / KC;
    float* C = Cpart + (size_t)blockIdx.z * MPAD * N;

    const unsigned* srcA[2] = { Ah + (size_t)m0 * Kw, Al + (size_t)m0 * Kw };
    const unsigned* srcB[2] = { Bh + (size_t)n0 * Kw, Bl + (size_t)n0 * Kw };

    auto issue = [&](int ch, int st) {
        int kbw = (kbase + ch * KC) >> 1;
#pragma unroll
        for (int i = 0; i < 4; i++) {
            int idx = t + (i & 1) * 256;
            int mat = i >> 1;
            int row = idx >> 2, q = idx & 3;
            const unsigned* src = srcA[mat] + (size_t)row * Kw + kbw + q * 4;
            uint32_t dst = sbase + (uint32_t)((st * STAGEW + mat * A_SZW + row * 24 + q * 4) << 2);
            asm volatile("cp.async.cg.shared.global [%0], [%1], 16;" :: "r"(dst), "l"(src));
        }
#pragma unroll
        for (int i = 0; i < 2; i++) {
            int mat = i;
            int row = t >> 2, q = t & 3;
            const unsigned* src = srcB[mat] + (size_t)row * Kw + kbw + q * 4;
            uint32_t dst = sbase + (uint32_t)((st * STAGEW + 2 * A_SZW + mat * B_SZW + row * 24 + q * 4) << 2);
            asm volatile("cp.async.cg.shared.global [%0], [%1], 16;" :: "r"(dst), "l"(src));
        }
        CPA_COMMIT();
    };

    float acc[2][4][4];
#pragma unroll
    for (int mt = 0; mt < 2; mt++)
#pragma unroll
        for (int nt = 0; nt < 4; nt++)
#pragma unroll
            for (int e = 0; e < 4; e++) acc[mt][nt][e] = 0.f;

    issue(0, 0);
    issue(1, 1);

    for (int ch = 0; ch < nch; ch++) {
        CPA_WAIT1();
        __syncthreads();
        const unsigned* SW = smw + (ch & 1) * STAGEW;
#pragma unroll
        for (int grp = 0; grp < 2; grp++) {
            const int go = grp * 8 + 2 * c;
            unsigned ahf[2][4], alf[2][4];
#pragma unroll
            for (int mt = 0; mt < 2; mt++) {
                int r = (wm * 32 + mt * 16 + g) * 24 + go;
                uint2 x0 = *reinterpret_cast<const uint2*>(&SW[r]);
                uint2 x1 = *reinterpret_cast<const uint2*>(&SW[r + 192]);
                ahf[mt][0] = x0.x; ahf[mt][1] = x1.x; ahf[mt][2] = x0.y; ahf[mt][3] = x1.y;
                uint2 y0 = *reinterpret_cast<const uint2*>(&SW[r + A_SZW]);
                uint2 y1 = *reinterpret_cast<const uint2*>(&SW[r + A_SZW + 192]);
                alf[mt][0] = y0.x; alf[mt][1] = y1.x; alf[mt][2] = y0.y; alf[mt][3] = y1.y;
            }
            uint2 bhf[4], blf[4];
#pragma unroll
            for (int nt = 0; nt < 4; nt++) {
                int n = (wn * 32 + nt * 8 + g) * 24 + go;
                bhf[nt] = *reinterpret_cast<const uint2*>(&SW[2 * A_SZW + n]);
                blf[nt] = *reinterpret_cast<const uint2*>(&SW[2 * A_SZW + B_SZW + n]);
            }
#pragma unroll
            for (int mt = 0; mt < 2; mt++)
#pragma unroll
                for (int nt = 0; nt < 4; nt++)
                    MMA_F16(acc[mt][nt], ahf[mt][0], ahf[mt][1], ahf[mt][2], ahf[mt][3],
                            bhf[nt].x, bhf[nt].y);
#pragma unroll
            for (int mt = 0; mt < 2; mt++)
#pragma unroll
                for (int nt = 0; nt < 4; nt++)
                    MMA_F16(acc[mt][nt], ahf[mt][0], ahf[mt][1], ahf[mt][2], ahf[mt][3],
                            blf[nt].x, blf[nt].y);
#pragma unroll
            for (int mt = 0; mt < 2; mt++)
#pragma unroll
                for (int nt = 0; nt < 4; nt++)
                    MMA_F16(acc[mt][nt], alf[mt][0], alf[mt][1], alf[mt][2], alf[mt][3],
                            bhf[nt].x, bhf[nt].y);
        }
        __syncthreads();
        if (ch + 2 < nch) issue(ch + 2, ch & 1);
        else CPA_COMMIT();
    }

#pragma unroll
    for (int mt = 0; mt < 2; mt++) {
        int row0 = m0 + wm * 32 + mt * 16 + g;
#pragma unroll
        for (int nt = 0; nt < 4; nt++) {
            int col = n0 + wn * 32 + nt * 8 + 2 * c;
            *reinterpret_cast<float2*>(&C[(size_t)row0 * N + col])
                = make_float2(acc[mt][nt][0], acc[mt][nt][1]);
            *reinterpret_cast<float2*>(&C[(size_t)(row0 + 8) * N + col])
                = make_float2(acc[mt][nt][2], acc[mt][nt][3]);
        }
    }
}

// ---------------- reduce1: (sum partials)/64 + bias -> fp16 split conv ----------------
__global__ void k_reduce1(const float* __restrict__ bias) {
    int i = blockIdx.x * blockDim.x + threadIdx.x;
    if (i >= MPAD * (KCONV / 16)) return;
    size_t o = (size_t)i * 16;
    int n0 = (i & 63) * 16;
    float v[16];
#pragma unroll
    for (int q = 0; q < 4; q++) {
        float4 a = *reinterpret_cast<const float4*>(&g_part[o + q * 4]);
        float4 b = *reinterpret_cast<const float4*>(&g_part[(size_t)MPAD * KCONV + o + q * 4]);
        float4 bv = *reinterpret_cast<const float4*>(&bias[n0 + q * 4]);
        v[q * 4 + 0] = (a.x + b.x) * BINV + bv.x;
        v[q * 4 + 1] = (a.y + b.y) * BINV + bv.y;
        v[q * 4 + 2] = (a.z + b.z) * BINV + bv.z;
        v[q * 4 + 3] = (a.w + b.w) * BINV + bv.w;
    }
    split16h_store(v, 1.0f, &g_convH16[o >> 1], &g_convL16[o >> 1]);
}

// ---------------- assemble (inline K-split reduce + descale of gemm2 partials) ----------------
__global__ void k_assemble(const float* __restrict__ anchd, float* __restrict__ out) {
    int row = blockIdx.x;
    int b = row / NEDGE, e = row % NEDGE;
    float* prop   = out + (size_t)b * NPROP * NPRED;
    float* scores = out + (size_t)NB * NPROP * NPRED + (size_t)NB * NPROP + (size_t)b * NPROP;
    const float* p0 = g_part + (size_t)row * NPAD;
    auto rcval = [&](int n) {
        float v = p0[n] + p0[(size_t)MPAD * NPAD + n];
        return v * BINV + g_bc[n];
    };
    for (int l = threadIdx.x; l < NANG * NPRED; l += blockDim.x) {
        int a = l / NPRED, q = l % NPRED;
        int p = e * NANG + a;
        float v;
        if (q < 2)      v = rcval(NREG + a * 2 + q);
        else if (q < 4) v = anchd[(size_t)p * NPRED + q];
        else            v = anchd[(size_t)p * NPRED + q] + rcval(a * 73 + (q - 4));
        prop[(size_t)p * NPRED + q] = v;
    }
    if (threadIdx.x < NANG) {
        int a = threadIdx.x;
        int p = e * NANG + a;
        float l0 = rcval(NREG + a * 2);
        float l1 = rcval(NREG + a * 2 + 1);
        scores[p] = 1.0f / (1.0f + expf(l0 - l1));
    }
}

// ---------------- NMS sort: rank + gather into strip-major xsT ----------------
__global__ __launch_bounds__(736) void k_sort(const float* __restrict__ out) {
    int b = blockIdx.x;
    __shared__ float s[NPROP];
    const float* scores = out + (size_t)NB * NPROP * NPRED + (size_t)NB * NPROP + (size_t)b * NPROP;
    const float* prop   = out + (size_t)b * NPROP * NPRED;
    int i = threadIdx.x;
    if (i < NPROP) s[i] = scores[i];
    __syncthreads();
    if (i < NPROP) {
        float si = s[i];
        int r = 0;
        for (int j = 0; j < NPROP; j++) {
            float sj = s[j];
            r += (sj > si) || (sj == si && j < i);
        }
        int base = b * NPROP;
        g_order[base + r] = i;
        float p2 = prop[(size_t)i * NPRED + 2];
        float p4 = prop[(size_t)i * NPRED + 4];
        float st = fminf(fmaxf(rintf(p2 * NSTRIPSF), 0.0f), NSTRIPSF);
        float en = fminf(fmaxf(st + p4 - 1.0f, 0.0f), NSTRIPSF);
        g_sstart[base + r] = st;
        g_send[base + r]   = en;
        float* dstT = g_sxsT + (size_t)b * NOFF * NPROP + r;   // [k][rank]
        const float* src = prop + (size_t)i * NPRED + 5;
        for (int k = 0; k < NOFF; k++) dstT[(size_t)k * NPROP] = src[k];
    }
}

// ---------------- NMS pairs: coalesced strip-major reads ----------------
__global__ void k_pairs() {
    int b    = blockIdx.y;
    int warp = threadIdx.x >> 5;
    int lane = threadIdx.x & 31;
    int i    = blockIdx.x * 8 + warp;
    if (i >= NPROP) return;
    int base = b * NPROP;
    const float* xsT = g_sxsT + (size_t)b * NOFF * NPROP;
    float si = g_sstart[base + i], ei = g_send[base + i];
    for (int jw = 0; jw < NWORDS; jw++) {
        int j = jw * 32 + lane;
        bool sup = false;
        if (j < NPROP) {
            float s  = fmaxf(si, g_sstart[base + j]);
            float e  = fminf(ei, g_send[base + j]);
            float cnt = e - s + 1.0f;
            if (cnt > 0.0f) {
                int k0 = (int)s;
                int k1 = (int)floorf(e);
                float sum = 0.0f;
                for (int k = k0; k <= k1; k++)
                    sum += fabsf(xsT[(size_t)k * NPROP + i] - xsT[(size_t)k * NPROP + j]);
                sup = (sum / fmaxf(cnt, 1.0f)) < NMS_T;
            }
        }
        unsigned m = __ballot_sync(0xFFFFFFFFu, sup);
        if (lane == 0) g_sup[(size_t)(base + i) * NWORDS + jw] = m;
    }
}

// ---------------- NMS scan: sequential, smem-staged ----------------
__global__ __launch_bounds__(256) void k_scan(float* __restrict__ out) {
    int b = blockIdx.x;
    __shared__ unsigned ssup[2][NCHUNK][NWORDS + 1];
    __shared__ int      sorder[NPROP];
    __shared__ float    skeep [NPROP];
    int t = threadIdx.x, lane = t & 31, warp = t >> 5;
    int base = b * NPROP;
    const unsigned* gs = g_sup + (size_t)base * NWORDS;

    for (int i = t; i < NPROP; i += 256) sorder[i] = g_order[base + i];
    for (int x = t; x < NCHUNK * NWORDS; x += 256)
        ssup[0][x / NWORDS][x % NWORDS] = gs[x];
    __syncthreads();

    unsigned my = 0;
    for (int c = 0; c < NCHUNKS; c++) {
        if (warp != 0) {
            if (c + 1 < NCHUNKS) {
                int i0 = (c + 1) * NCHUNK;
                int cnt = min(NCHUNK, NPROP - i0) * NWORDS;
                int tt = t - 32;
                for (int x = tt; x < cnt; x += 224)
                    ssup[(c + 1) & 1][x / NWORDS][x % NWORDS] = gs[(size_t)i0 * NWORDS + x];
            }
        } else {
            int i1 = min(NPROP, (c + 1) * NCHUNK);
            int lw = (lane < NWORDS) ? lane : 0;
            for (int i = c * NCHUNK; i < i1; i++) {
                unsigned row = ssup[c & 1][i - c * NCHUNK][lw];
                int wi = i >> 5, bit = i & 31;
                unsigned wsup = __shfl_sync(0xFFFFFFFFu, my, wi);
                bool kept = ((wsup >> bit) & 1u) == 0u;
                if (kept) {
                    unsigned m;
                    if (lane > wi)       m = 0xFFFFFFFFu;
                    else if (lane == wi) m = (bit == 31) ? 0u : (0xFFFFFFFFu << (bit + 1));
                    else                 m = 0u;
                    my |= row & m;
                }
                if (lane == 0) skeep[sorder[i]] = kept ? 1.0f : 0.0f;
            }
        }
        __syncthreads();
    }
    float* keep = out + (size_t)NB * NPROP * NPRED + (size_t)b * NPROP;
    for (int i = t; i < NPROP; i += 256) keep[i] = skeep[i];
}

// ---------------- launcher ----------------
extern "C" void kernel_launch(void* const* d_in, const int* in_sizes, int n_in,
                              void* d_out, int out_size) {
    const float* feat   = (const float*)d_in[0];
    const float* W_conv = (const float*)d_in[1];
    const float* b_conv = (const float*)d_in[2];
    const float* W_cls  = (const float*)d_in[3];
    const float* b_cls  = (const float*)d_in[4];
    const float* W_reg  = (const float*)d_in[5];
    const float* b_reg  = (const float*)d_in[6];
    const float* anchd  = (const float*)d_in[8];
    float* out = (float*)d_out;

    void *pFH, *pFL, *pWH, *pWL, *pCH, *pCL, *pWcH, *pWcL, *pPart;
    cudaGetSymbolAddress(&pFH,  g_featH16);
    cudaGetSymbolAddress(&pFL,  g_featL16);
    cudaGetSymbolAddress(&pWH,  g_WconvH16);
    cudaGetSymbolAddress(&pWL,  g_WconvL16);
    cudaGetSymbolAddress(&pCH,  g_convH16);
    cudaGetSymbolAddress(&pCL,  g_convL16);
    cudaGetSymbolAddress(&pWcH, g_WcH16);
    cudaGetSymbolAddress(&pWcL, g_WcL16);
    cudaGetSymbolAddress(&pPart, g_part);

    cudaFuncSetAttribute(k_gemm_f16, cudaFuncAttributeMaxDynamicSharedMemorySize, GEMM_SMEM);

    k_prep<<<(PREP_TOTAL + 255) / 256, 256>>>(W_reg, b_reg, W_cls, b_cls, W_conv, feat);

    k_gemm_f16<<<dim3(KCONV / 64, MPAD / 128, KSPLIT), 256, GEMM_SMEM>>>(
        (const unsigned*)pFH, (const unsigned*)pFL,
        (const unsigned*)pWH, (const unsigned*)pWL,
        (float*)pPart, KBACK, KCONV);
    k_reduce1<<<(MPAD * (KCONV / 16) + 255) / 256, 256>>>(b_conv);

    k_gemm_f16<<<dim3(NPAD / 64, MPAD / 128, KSPLIT), 256, GEMM_SMEM>>>(
        (const unsigned*)pCH, (const unsigned*)pCL,
        (const unsigned*)pWcH, (const unsigned*)pWcL,
        (float*)pPart, KCONV, NPAD);

    k_assemble<<<MROWS, 256>>>(anchd, out);
    k_sort<<<NB, 736>>>(out);
    k_pairs<<<dim3((NPROP + 7) / 8, NB), 256>>>();
    k_scan<<<NB, 256>>>(out);
}

// round 15
// speedup vs baseline: 1.4690x; 1.0132x over previous
#include <cuda_runtime.h>
#include <cuda_fp16.h>
#include <math.h>
#include <stdint.h>

// ---------------- problem constants ----------------
#define NB      32
#define FH      11
#define FW      20
#define NEDGE   42
#define NANG    17
#define NPRED   77
#define NPROP   714
#define NOFF    72
#define KBACK   512
#define KCONV   1024
#define NREG    1241
#define NCLS    34
#define NPAD    1280
#define MROWS   1344
#define MPAD    1408
#define NWORDS  23
#define NSTRIPSF 71.0f
#define NMS_T   15.0f
#define NCHUNK  128
#define NCHUNKS 6
#define KC      32          // K per pipeline chunk (2 k16 mma groups)
#define BSCALE  64.0f
#define BINV    (1.0f / 64.0f)
#define A_SZW   3072        // 128 * 24
#define B_SZW   1536        // 64 * 24
#define STAGEW  9216
#define GEMM_SMEM (2 * STAGEW * 4)   // 73728 bytes
#define KCH     12          // sort transpose chunk (72 = 6*12)

// prep partition (16-float groups)
#define PREP_W  (NPAD * (KCONV / 16))
#define PREP_S  (KCONV * (KBACK / 16))
#define PREP_G  (MROWS * (KBACK / 16))
#define PREP_TOTAL (PREP_W + PREP_S + PREP_G)

// ---------------- scratch ----------------
__device__ __align__(16) unsigned g_featH16 [MPAD * KBACK / 2];
__device__ __align__(16) unsigned g_featL16 [MPAD * KBACK / 2];
__device__ __align__(16) unsigned g_WconvH16[KCONV * KBACK / 2];
__device__ __align__(16) unsigned g_WconvL16[KCONV * KBACK / 2];
__device__ __align__(16) unsigned g_convH16 [MPAD * KCONV / 2];
__device__ __align__(16) unsigned g_convL16 [MPAD * KCONV / 2];
__device__ __align__(16) unsigned g_WcH16   [NPAD * KCONV / 2];
__device__ __align__(16) unsigned g_WcL16   [NPAD * KCONV / 2];
__device__ float    g_bc    [NPAD];
__device__ float    g_part  [2 * MPAD * NPAD];
__device__ int      g_order [NB * NPROP];
__device__ float    g_sstart[NB * NPROP];
__device__ float    g_send  [NB * NPROP];
__device__ float    g_sxsT  [NB * NOFF * NPROP];   // strip-major: [b][k][rank]
__device__ unsigned g_sup   [NB * NPROP * NWORDS];

// ---------------- helpers ----------------
__device__ __forceinline__ unsigned pack2h(float x0, float x1) {
    __half h0 = __float2half_rn(x0), h1 = __float2half_rn(x1);
    return (unsigned)__half_as_ushort(h0) | ((unsigned)__half_as_ushort(h1) << 16);
}
__device__ __forceinline__ void split16h_store(const float* v, float s,
                                               unsigned* H, unsigned* L) {
    unsigned hw[8], lw[8];
#pragma unroll
    for (int p = 0; p < 8; p++) {
        float x0 = v[2 * p] * s, x1 = v[2 * p + 1] * s;
        __half h0 = __float2half_rn(x0), h1 = __float2half_rn(x1);
        float l0 = x0 - __half2float(h0), l1 = x1 - __half2float(h1);
        hw[p] = (unsigned)__half_as_ushort(h0) | ((unsigned)__half_as_ushort(h1) << 16);
        lw[p] = pack2h(l0, l1);
    }
    *reinterpret_cast<uint4*>(H)     = make_uint4(hw[0], hw[4], hw[1], hw[5]);
    *reinterpret_cast<uint4*>(H + 4) = make_uint4(hw[2], hw[6], hw[3], hw[7]);
    *reinterpret_cast<uint4*>(L)     = make_uint4(lw[0], lw[4], lw[1], lw[5]);
    *reinterpret_cast<uint4*>(L + 4) = make_uint4(lw[2], lw[6], lw[3], lw[7]);
}
__device__ __forceinline__ uint32_t smem_u32(const void* p) {
    uint32_t a;
    asm("{ .reg .u64 tmp; cvta.to.shared.u64 tmp, %1; cvt.u32.u64 %0, tmp; }"
        : "=r"(a) : "l"(p));
    return a;
}
#define MMA_F16(d, a0, a1, a2, a3, b0, b1)                                       \
    asm volatile("mma.sync.aligned.m16n8k16.row.col.f32.f16.f16.f32 "            \
        "{%0,%1,%2,%3}, {%4,%5,%6,%7}, {%8,%9}, {%0,%1,%2,%3};"                  \
        : "+f"((d)[0]), "+f"((d)[1]), "+f"((d)[2]), "+f"((d)[3])                 \
        : "r"(a0), "r"(a1), "r"(a2), "r"(a3), "r"(b0), "r"(b1))
#define CPA_COMMIT() asm volatile("cp.async.commit_group;" ::: "memory")
#define CPA_WAIT1()  asm volatile("cp.async.wait_group 1;" ::: "memory")

// ---------------- fused prep ----------------
__global__ void k_prep(const float* __restrict__ Wr, const float* __restrict__ br,
                       const float* __restrict__ Wc, const float* __restrict__ bc,
                       const float* __restrict__ Wconv, const float* __restrict__ feat) {
    int i = blockIdx.x * blockDim.x + threadIdx.x;
    if (i < PREP_W) {
        int row = i >> 6, k0 = (i & 63) * 16;
        float v[16];
#pragma unroll
        for (int q = 0; q < 16; q++) v[q] = 0.f;
        if (row < NREG) {
#pragma unroll
            for (int q = 0; q < 4; q++)
                *reinterpret_cast<float4*>(v + q * 4) =
                    *reinterpret_cast<const float4*>(&Wr[(size_t)row * KCONV + k0 + q * 4]);
        } else if (row < NREG + NCLS) {
#pragma unroll
            for (int q = 0; q < 4; q++)
                *reinterpret_cast<float4*>(v + q * 4) =
                    *reinterpret_cast<const float4*>(&Wc[(size_t)(row - NREG) * KCONV + k0 + q * 4]);
        }
        size_t o = ((size_t)row * KCONV + k0) >> 1;
        split16h_store(v, BSCALE, &g_WcH16[o], &g_WcL16[o]);
        if (i < NPAD) {
            float b = 0.f;
            if (i < NREG)             b = br[i];
            else if (i < NREG + NCLS) b = bc[i - NREG];
            g_bc[i] = b;
        }
        return;
    }
    i -= PREP_W;
    if (i < PREP_S) {
        size_t o = (size_t)i * 16;
        float v[16];
#pragma unroll
        for (int q = 0; q < 4; q++)
            *reinterpret_cast<float4*>(v + q * 4) =
                *reinterpret_cast<const float4*>(&Wconv[o + q * 4]);
        split16h_store(v, BSCALE, &g_WconvH16[o >> 1], &g_WconvL16[o >> 1]);
        return;
    }
    i -= PREP_S;
    if (i < PREP_G) {
        int m = i >> 5, c0 = (i & 31) * 16;
        int b = m / NEDGE, e = m % NEDGE;
        int h, w;
        if (e < FH)        { h = e;      w = 0;        }
        else if (e < 2*FH) { h = e - FH; w = FW - 1;   }
        else               { h = FH - 1; w = e - 2*FH; }
        float v[16];
#pragma unroll
        for (int j = 0; j < 16; j++)
            v[j] = feat[((size_t)(b * KBACK + c0 + j) * FH + h) * FW + w];
        size_t o = ((size_t)m * KBACK + c0) >> 1;
        split16h_store(v, 1.0f, &g_featH16[o], &g_featL16[o]);
    }
}

// ---------------- fp16 mma.sync GEMM, 3-term split, 2-stage cp.async ----------------
template<int NSPLIT>
__global__ __launch_bounds__(256, 3) void k_gemm_f16(
    const unsigned* __restrict__ Ah, const unsigned* __restrict__ Al,
    const unsigned* __restrict__ Bh, const unsigned* __restrict__ Bl,
    float* __restrict__ Cpart, int K, int N)
{
    extern __shared__ unsigned smw[];
    const uint32_t sbase = smem_u32(smw);
    const int m0 = blockIdx.y * 128, n0 = blockIdx.x * 64;
    const int t = threadIdx.x, w = t >> 5, lane = t & 31;
    const int g = lane >> 2, c = lane & 3;
    const int wm = w >> 1, wn = w & 1;
    const int Kw = K >> 1;
    const int kbase = blockIdx.z * (K / NSPLIT);
    const int nch = (K / NSPLIT) / KC;
    float* C = Cpart + (size_t)blockIdx.z * MPAD * N;

    const unsigned* srcA[2] = { Ah + (size_t)m0 * Kw, Al + (size_t)m0 * Kw };
    const unsigned* srcB[2] = { Bh + (size_t)n0 * Kw, Bl + (size_t)n0 * Kw };

    auto issue = [&](int ch, int st) {
        int kbw = (kbase + ch * KC) >> 1;
#pragma unroll
        for (int i = 0; i < 4; i++) {
            int idx = t + (i & 1) * 256;
            int mat = i >> 1;
            int row = idx >> 2, q = idx & 3;
            const unsigned* src = srcA[mat] + (size_t)row * Kw + kbw + q * 4;
            uint32_t dst = sbase + (uint32_t)((st * STAGEW + mat * A_SZW + row * 24 + q * 4) << 2);
            asm volatile("cp.async.cg.shared.global [%0], [%1], 16;" :: "r"(dst), "l"(src));
        }
#pragma unroll
        for (int i = 0; i < 2; i++) {
            int mat = i;
            int row = t >> 2, q = t & 3;
            const unsigned* src = srcB[mat] + (size_t)row * Kw + kbw + q * 4;
            uint32_t dst = sbase + (uint32_t)((st * STAGEW + 2 * A_SZW + mat * B_SZW + row * 24 + q * 4) << 2);
            asm volatile("cp.async.cg.shared.global [%0], [%1], 16;" :: "r"(dst), "l"(src));
        }
        CPA_COMMIT();
    };

    float acc[2][4][4];
#pragma unroll
    for (int mt = 0; mt < 2; mt++)
#pragma unroll
        for (int nt = 0; nt < 4; nt++)
#pragma unroll
            for (int e = 0; e < 4; e++) acc[mt][nt][e] = 0.f;

    issue(0, 0);
    issue(1, 1);

    for (int ch = 0; ch < nch; ch++) {
        CPA_WAIT1();
        __syncthreads();
        const unsigned* SW = smw + (ch & 1) * STAGEW;
#pragma unroll
        for (int grp = 0; grp < 2; grp++) {
            const int go = grp * 8 + 2 * c;
            unsigned ahf[2][4], alf[2][4];
#pragma unroll
            for (int mt = 0; mt < 2; mt++) {
                int r = (wm * 32 + mt * 16 + g) * 24 + go;
                uint2 x0 = *reinterpret_cast<const uint2*>(&SW[r]);
                uint2 x1 = *reinterpret_cast<const uint2*>(&SW[r + 192]);
                ahf[mt][0] = x0.x; ahf[mt][1] = x1.x; ahf[mt][2] = x0.y; ahf[mt][3] = x1.y;
                uint2 y0 = *reinterpret_cast<const uint2*>(&SW[r + A_SZW]);
                uint2 y1 = *reinterpret_cast<const uint2*>(&SW[r + A_SZW + 192]);
                alf[mt][0] = y0.x; alf[mt][1] = y1.x; alf[mt][2] = y0.y; alf[mt][3] = y1.y;
            }
            uint2 bhf[4], blf[4];
#pragma unroll
            for (int nt = 0; nt < 4; nt++) {
                int n = (wn * 32 + nt * 8 + g) * 24 + go;
                bhf[nt] = *reinterpret_cast<const uint2*>(&SW[2 * A_SZW + n]);
                blf[nt] = *reinterpret_cast<const uint2*>(&SW[2 * A_SZW + B_SZW + n]);
            }
#pragma unroll
            for (int mt = 0; mt < 2; mt++)
#pragma unroll
                for (int nt = 0; nt < 4; nt++)
                    MMA_F16(acc[mt][nt], ahf[mt][0], ahf[mt][1], ahf[mt][2], ahf[mt][3],
                            bhf[nt].x, bhf[nt].y);
#pragma unroll
            for (int mt = 0; mt < 2; mt++)
#pragma unroll
                for (int nt = 0; nt < 4; nt++)
                    MMA_F16(acc[mt][nt], ahf[mt][0], ahf[mt][1], ahf[mt][2], ahf[mt][3],
                            blf[nt].x, blf[nt].y);
#pragma unroll
            for (int mt = 0; mt < 2; mt++)
#pragma unroll
                for (int nt = 0; nt < 4; nt++)
                    MMA_F16(acc[mt][nt], alf[mt][0], alf[mt][1], alf[mt][2], alf[mt][3],
                            bhf[nt].x, bhf[nt].y);
        }
        __syncthreads();
        if (ch + 2 < nch) issue(ch + 2, ch & 1);
        else CPA_COMMIT();
    }

#pragma unroll
    for (int mt = 0; mt < 2; mt++) {
        int row0 = m0 + wm * 32 + mt * 16 + g;
#pragma unroll
        for (int nt = 0; nt < 4; nt++) {
            int col = n0 + wn * 32 + nt * 8 + 2 * c;
            *reinterpret_cast<float2*>(&C[(size_t)row0 * N + col])
                = make_float2(acc[mt][nt][0], acc[mt][nt][1]);
            *reinterpret_cast<float2*>(&C[(size_t)(row0 + 8) * N + col])
                = make_float2(acc[mt][nt][2], acc[mt][nt][3]);
        }
    }
}

// ---------------- reduce1: partial/64 + bias -> fp16 split conv (single buffer) ----------------
__global__ void k_reduce1(const float* __restrict__ bias) {
    int i = blockIdx.x * blockDim.x + threadIdx.x;
    if (i >= MPAD * (KCONV / 16)) return;
    size_t o = (size_t)i * 16;
    int n0 = (i & 63) * 16;
    float v[16];
#pragma unroll
    for (int q = 0; q < 4; q++) {
        float4 a  = *reinterpret_cast<const float4*>(&g_part[o + q * 4]);
        float4 bv = *reinterpret_cast<const float4*>(&bias[n0 + q * 4]);
        v[q * 4 + 0] = a.x * BINV + bv.x;
        v[q * 4 + 1] = a.y * BINV + bv.y;
        v[q * 4 + 2] = a.z * BINV + bv.z;
        v[q * 4 + 3] = a.w * BINV + bv.w;
    }
    split16h_store(v, 1.0f, &g_convH16[o >> 1], &g_convL16[o >> 1]);
}

// ---------------- assemble: warp = angle, lane = q (no div/mod) ----------------
__global__ __launch_bounds__(544) void k_assemble(const float* __restrict__ anchd,
                                                  float* __restrict__ out) {
    int row = blockIdx.x;
    int b = row / NEDGE, e = row % NEDGE;
    float* prop   = out + (size_t)b * NPROP * NPRED;
    float* scores = out + (size_t)NB * NPROP * NPRED + (size_t)NB * NPROP + (size_t)b * NPROP;
    const float* p0 = g_part + (size_t)row * NPAD;
    auto rcval = [&](int n) {
        float v = p0[n] + p0[(size_t)MPAD * NPAD + n];
        return v * BINV + g_bc[n];
    };
    int a = threadIdx.x >> 5, lane = threadIdx.x & 31;
    int p = e * NANG + a;
#pragma unroll
    for (int qi = 0; qi < 3; qi++) {
        int q = lane + qi * 32;
        if (q >= NPRED) break;
        float v;
        if (q < 2)      v = rcval(NREG + a * 2 + q);
        else if (q < 4) v = anchd[(size_t)p * NPRED + q];
        else            v = anchd[(size_t)p * NPRED + q] + rcval(a * 73 + (q - 4));
        prop[(size_t)p * NPRED + q] = v;
    }
    if (lane == 0) {
        float l0 = rcval(NREG + a * 2);
        float l1 = rcval(NREG + a * 2 + 1);
        scores[p] = 1.0f / (1.0f + expf(l0 - l1));
    }
}

// ---------------- NMS sort: rank + staged coalesced transpose into xsT ----------------
__global__ __launch_bounds__(736) void k_sort(const float* __restrict__ out) {
    __shared__ float s[NPROP];
    __shared__ int   sorder[NPROP];
    __shared__ float sxbuf[KCH * NPROP];
    int b = blockIdx.x;
    const float* scores = out + (size_t)NB * NPROP * NPRED + (size_t)NB * NPROP + (size_t)b * NPROP;
    const float* prop   = out + (size_t)b * NPROP * NPRED;
    int t = threadIdx.x;
    if (t < NPROP) s[t] = scores[t];
    __syncthreads();
    if (t < NPROP) {
        float si = s[t];
        int r = 0;
        for (int j = 0; j < NPROP; j++) {
            float sj = s[j];
            r += (sj > si) || (sj == si && j < t);
        }
        int base = b * NPROP;
        g_order[base + r] = t;
        sorder[r] = t;
        float p2 = prop[(size_t)t * NPRED + 2];
        float p4 = prop[(size_t)t * NPRED + 4];
        float st = fminf(fmaxf(rintf(p2 * NSTRIPSF), 0.0f), NSTRIPSF);
        float en = fminf(fmaxf(st + p4 - 1.0f, 0.0f), NSTRIPSF);
        g_sstart[base + r] = st;
        g_send[base + r]   = en;
    }
    __syncthreads();
    // transpose prop xs (original order) -> xsT[k][rank], chunked by KCH strips
    float* xsT = g_sxsT + (size_t)b * NOFF * NPROP;
    for (int k0 = 0; k0 < NOFF; k0 += KCH) {
        // load: idx = i*KCH + kk ; consecutive threads read consecutive kk of row i
        for (int idx = t; idx < NPROP * KCH; idx += 736) {
            int i = idx / KCH, kk = idx % KCH;
            sxbuf[kk * NPROP + i] = prop[(size_t)i * NPRED + 5 + k0 + kk];
        }
        __syncthreads();
        // write: idx = kk*NPROP + r ; consecutive threads write consecutive r
        for (int idx = t; idx < KCH * NPROP; idx += 736) {
            int kk = idx / NPROP, r = idx % NPROP;
            xsT[(size_t)(k0 + kk) * NPROP + r] = sxbuf[kk * NPROP + sorder[r]];
        }
        __syncthreads();
    }
}

// ---------------- NMS pairs: coalesced strip-major reads ----------------
__global__ void k_pairs() {
    int b    = blockIdx.y;
    int warp = threadIdx.x >> 5;
    int lane = threadIdx.x & 31;
    int i    = blockIdx.x * 8 + warp;
    if (i >= NPROP) return;
    int base = b * NPROP;
    const float* xsT = g_sxsT + (size_t)b * NOFF * NPROP;
    float si = g_sstart[base + i], ei = g_send[base + i];
    for (int jw = 0; jw < NWORDS; jw++) {
        int j = jw * 32 + lane;
        bool sup = false;
        if (j < NPROP) {
            float s  = fmaxf(si, g_sstart[base + j]);
            float e  = fminf(ei, g_send[base + j]);
            float cnt = e - s + 1.0f;
            if (cnt > 0.0f) {
                int k0 = (int)s;
                int k1 = (int)floorf(e);
                float sum = 0.0f;
                for (int k = k0; k <= k1; k++)
                    sum += fabsf(xsT[(size_t)k * NPROP + i] - xsT[(size_t)k * NPROP + j]);
                sup = (sum / fmaxf(cnt, 1.0f)) < NMS_T;
            }
        }
        unsigned m = __ballot_sync(0xFFFFFFFFu, sup);
        if (lane == 0) g_sup[(size_t)(base + i) * NWORDS + jw] = m;
    }
}

// ---------------- NMS scan: sequential, smem-staged ----------------
__global__ __launch_bounds__(256) void k_scan(float* __restrict__ out) {
    int b = blockIdx.x;
    __shared__ unsigned ssup[2][NCHUNK][NWORDS + 1];
    __shared__ int      sorder[NPROP];
    __shared__ float    skeep [NPROP];
    int t = threadIdx.x, lane = t & 31, warp = t >> 5;
    int base = b * NPROP;
    const unsigned* gs = g_sup + (size_t)base * NWORDS;

    for (int i = t; i < NPROP; i += 256) sorder[i] = g_order[base + i];
    for (int x = t; x < NCHUNK * NWORDS; x += 256)
        ssup[0][x / NWORDS][x % NWORDS] = gs[x];
    __syncthreads();

    unsigned my = 0;
    for (int c = 0; c < NCHUNKS; c++) {
        if (warp != 0) {
            if (c + 1 < NCHUNKS) {
                int i0 = (c + 1) * NCHUNK;
                int cnt = min(NCHUNK, NPROP - i0) * NWORDS;
                int tt = t - 32;
                for (int x = tt; x < cnt; x += 224)
                    ssup[(c + 1) & 1][x / NWORDS][x % NWORDS] = gs[(size_t)i0 * NWORDS + x];
            }
        } else {
            int i1 = min(NPROP, (c + 1) * NCHUNK);
            int lw = (lane < NWORDS) ? lane : 0;
            for (int i = c * NCHUNK; i < i1; i++) {
                unsigned row = ssup[c & 1][i - c * NCHUNK][lw];
                int wi = i >> 5, bit = i & 31;
                unsigned wsup = __shfl_sync(0xFFFFFFFFu, my, wi);
                bool kept = ((wsup >> bit) & 1u) == 0u;
                if (kept) {
                    unsigned m;
                    if (lane > wi)       m = 0xFFFFFFFFu;
                    else if (lane == wi) m = (bit == 31) ? 0u : (0xFFFFFFFFu << (bit + 1));
                    else                 m = 0u;
                    my |= row & m;
                }
                if (lane == 0) skeep[sorder[i]] = kept ? 1.0f : 0.0f;
            }
        }
        __syncthreads();
    }
    float* keep = out + (size_t)NB * NPROP * NPRED + (size_t)b * NPROP;
    for (int i = t; i < NPROP; i += 256) keep[i] = skeep[i];
}

// ---------------- launcher ----------------
extern "C" void kernel_launch(void* const* d_in, const int* in_sizes, int n_in,
                              void* d_out, int out_size) {
    const float* feat   = (const float*)d_in[0];
    const float* W_conv = (const float*)d_in[1];
    const float* b_conv = (const float*)d_in[2];
    const float* W_cls  = (const float*)d_in[3];
    const float* b_cls  = (const float*)d_in[4];
    const float* W_reg  = (const float*)d_in[5];
    const float* b_reg  = (const float*)d_in[6];
    const float* anchd  = (const float*)d_in[8];
    float* out = (float*)d_out;

    void *pFH, *pFL, *pWH, *pWL, *pCH, *pCL, *pWcH, *pWcL, *pPart;
    cudaGetSymbolAddress(&pFH,  g_featH16);
    cudaGetSymbolAddress(&pFL,  g_featL16);
    cudaGetSymbolAddress(&pWH,  g_WconvH16);
    cudaGetSymbolAddress(&pWL,  g_WconvL16);
    cudaGetSymbolAddress(&pCH,  g_convH16);
    cudaGetSymbolAddress(&pCL,  g_convL16);
    cudaGetSymbolAddress(&pWcH, g_WcH16);
    cudaGetSymbolAddress(&pWcL, g_WcL16);
    cudaGetSymbolAddress(&pPart, g_part);

    cudaFuncSetAttribute(k_gemm_f16<1>, cudaFuncAttributeMaxDynamicSharedMemorySize, GEMM_SMEM);
    cudaFuncSetAttribute(k_gemm_f16<2>, cudaFuncAttributeMaxDynamicSharedMemorySize, GEMM_SMEM);

    k_prep<<<(PREP_TOTAL + 255) / 256, 256>>>(W_reg, b_reg, W_cls, b_cls, W_conv, feat);

    // GEMM1 (no K-split): feat(1408x512) @ (64*W_conv)^T -> exact partials -> conv fp16
    k_gemm_f16<1><<<dim3(KCONV / 64, MPAD / 128, 1), 256, GEMM_SMEM>>>(
        (const unsigned*)pFH, (const unsigned*)pFL,
        (const unsigned*)pWH, (const unsigned*)pWL,
        (float*)pPart, KBACK, KCONV);
    k_reduce1<<<(MPAD * (KCONV / 16) + 255) / 256, 256>>>(b_conv);

    // GEMM2 (K-split x2): conv(1408x1024) @ (64*Wc)^T -> partials (reduced in assemble)
    k_gemm_f16<2><<<dim3(NPAD / 64, MPAD / 128, 2), 256, GEMM_SMEM>>>(
        (const unsigned*)pCH, (const unsigned*)pCL,
        (const unsigned*)pWcH, (const unsigned*)pWcL,
        (float*)pPart, KCONV, NPAD);

    k_assemble<<<MROWS, 544>>>(anchd, out);
    k_sort<<<NB, 736>>>(out);
    k_pairs<<<dim3((NPROP + 7) / 8, NB), 256>>>();
    k_scan<<<NB, 256>>>(out);
}